// round 13
// baseline (speedup 1.0000x reference)
#include <cuda_runtime.h>
#include <cuda_bf16.h>
#include <cuda_fp16.h>
#include <math.h>
#include <stdint.h>

#define BB 2
#define LL 2048
#define DD 1024
#define HH 16
#define DK 64
#define BL (BB*LL)              // 4096

typedef unsigned int u32;
typedef __nv_bfloat16 bf16;

// ---------------- scratch (device globals; no allocation allowed) ----------
__device__ __half g_P[(size_t)BB*HH*LL*LL];      // 256 MB e/probs (fp16, in place)
__device__ float  g_Tm[(size_t)BB*HH*16*LL];     // per-(row, n-tile) max
__device__ float  g_Ts[(size_t)BB*HH*16*LL];     // per-(row, n-tile) sum of e
__device__ bf16   g_xhi [BL*DD], g_xlo [BL*DD];
__device__ bf16   g_xshi[BL*DD], g_xslo[BL*DD];  // x * delta
__device__ bf16   g_Whi[3*DD*DD], g_Wlo[3*DD*DD]; // Wq/Wk/Wv hi/lo [k][n]
__device__ __half g_Wo16[DD*DD];                 // Wo fp16
__device__ bf16   g_Qhi[BL*DD], g_Qlo[BL*DD];
__device__ bf16   g_Khi[BL*DD], g_Klo[BL*DD];
__device__ __half g_V[BL*DD];                    // V fp16
__device__ __half g_C16[BL*DD];                  // context fp16

// ---------------- ptx helpers ----------------------------------------------
__device__ __forceinline__ u32 smem_u32(const void* p) {
    u32 a;
    asm("{ .reg .u64 t; cvta.to.shared.u64 t, %1; cvt.u32.u64 %0, t; }"
        : "=r"(a) : "l"(p));
    return a;
}

#define LDSM4(R0,R1,R2,R3,ADDR) \
    asm volatile("ldmatrix.sync.aligned.m8n8.x4.shared.b16 {%0,%1,%2,%3}, [%4];" \
        : "=r"(R0),"=r"(R1),"=r"(R2),"=r"(R3) : "r"(ADDR))
#define LDSM4T(R0,R1,R2,R3,ADDR) \
    asm volatile("ldmatrix.sync.aligned.m8n8.x4.trans.shared.b16 {%0,%1,%2,%3}, [%4];" \
        : "=r"(R0),"=r"(R1),"=r"(R2),"=r"(R3) : "r"(ADDR))

__device__ __forceinline__ void mma16816(float* c, const u32* a, const u32* b) {
    asm volatile(
        "mma.sync.aligned.m16n8k16.row.col.f32.bf16.bf16.f32 "
        "{%0,%1,%2,%3}, {%4,%5,%6,%7}, {%8,%9}, {%0,%1,%2,%3};"
        : "+f"(c[0]), "+f"(c[1]), "+f"(c[2]), "+f"(c[3])
        : "r"(a[0]), "r"(a[1]), "r"(a[2]), "r"(a[3]), "r"(b[0]), "r"(b[1]));
}

__device__ __forceinline__ void mma16816h(float* c, const u32* a, const u32* b) {
    asm volatile(
        "mma.sync.aligned.m16n8k16.row.col.f32.f16.f16.f32 "
        "{%0,%1,%2,%3}, {%4,%5,%6,%7}, {%8,%9}, {%0,%1,%2,%3};"
        : "+f"(c[0]), "+f"(c[1]), "+f"(c[2]), "+f"(c[3])
        : "r"(a[0]), "r"(a[1]), "r"(a[2]), "r"(a[3]), "r"(b[0]), "r"(b[1]));
}

#define CPA16(dst, src) \
    asm volatile("cp.async.cg.shared.global [%0], [%1], 16;" :: "r"(dst), "l"(src))
#define CPCOMMIT() asm volatile("cp.async.commit_group;" ::: "memory")
#define CPWAIT(n)  asm volatile("cp.async.wait_group %0;" :: "n"(n) : "memory")

// ---------------- async staging (swizzled) ----------------------------------
__device__ __forceinline__ void issue_A128(u32 dst, const bf16* A, size_t lda) {
#pragma unroll
    for (int i = 0; i < 4; i++) {
        int idx = threadIdx.x + (i << 8);
        int r = idx >> 3, c = idx & 7;
        int off = (r << 7) | (c << 4);
        CPA16(dst + (off ^ ((off >> 3) & 0x70)), A + (size_t)r * lda + (c << 3));
    }
}
__device__ __forceinline__ void issue_A256(u32 dst, const bf16* A, size_t lda) {
#pragma unroll
    for (int i = 0; i < 8; i++) {
        int idx = threadIdx.x + (i << 8);
        int r = idx >> 3, c = idx & 7;
        int off = (r << 7) | (c << 4);
        CPA16(dst + (off ^ ((off >> 3) & 0x70)), A + (size_t)r * lda + (c << 3));
    }
}
__device__ __forceinline__ void issue_B256(u32 dst, const bf16* B, size_t ldb) {
#pragma unroll
    for (int i = 0; i < 4; i++) {
        int idx = threadIdx.x + (i << 8);
        int r = idx >> 4, c = idx & 15;
        int off = (r << 8) | (c << 4);
        CPA16(dst + (off ^ ((off >> 4) & 0x70)), B + (size_t)r * ldb + (c << 3));
    }
}
__device__ __forceinline__ void issue_B64(u32 dst, const bf16* B, size_t ldb) {
#pragma unroll
    for (int i = 0; i < 2; i++) {
        int idx = threadIdx.x + (i << 8);
        int r = idx >> 3, c = idx & 7;
        int off = (r << 7) | (c << 4);
        CPA16(dst + (off ^ ((off >> 3) & 0x70)), B + (size_t)r * ldb + (c << 3));
    }
}

// ---------------- warp slab: 64x32 warp tile, 3-pass bf16 hi/lo ------------
template<int SW, int BMODE, int BPITCH>
__device__ __forceinline__ void warp_slab(
    u32 sAh, u32 sAl, u32 sBh, u32 sBl,
    int mwarp, int nwarp, int lane, float acc[4][4][4])
{
#pragma unroll
    for (int ks = 0; ks < 4; ks++) {
        const int k0 = ks << 4;
        u32 bh[4][2], bl[4][2], a[4][4];
#pragma unroll
        for (int nf = 0; nf < 2; nf++) {
            int off;
            if (BMODE == 0) {
                int kr = k0 + (lane & 15);
                int nc = nwarp + (nf << 4) + ((lane >> 4) << 3);
                off = kr * BPITCH + (nc << 1);
            } else {
                int nr = nwarp + (nf << 4) + (lane & 7) + ((lane >> 4) << 3);
                int kc = k0 + (((lane >> 3) & 1) << 3);
                off = (nr << 7) + (kc << 1);
            }
            int so = off ^ ((off >> SW) & 0x70);
            if (BMODE == 0) {
                LDSM4T(bh[nf*2][0], bh[nf*2][1], bh[nf*2+1][0], bh[nf*2+1][1], sBh + so);
                LDSM4T(bl[nf*2][0], bl[nf*2][1], bl[nf*2+1][0], bl[nf*2+1][1], sBl + so);
            } else {
                LDSM4(bh[nf*2][0], bh[nf*2][1], bh[nf*2+1][0], bh[nf*2+1][1], sBh + so);
                LDSM4(bl[nf*2][0], bl[nf*2][1], bl[nf*2+1][0], bl[nf*2+1][1], sBl + so);
            }
        }
        int arow = mwarp + (lane & 15);
        int acol = (k0 + ((lane >> 4) << 3)) << 1;
#pragma unroll
        for (int mf = 0; mf < 4; mf++) {
            int off = ((arow + (mf << 4)) << 7) + acol;
            int so = off ^ ((off >> 3) & 0x70);
            LDSM4(a[mf][0], a[mf][1], a[mf][2], a[mf][3], sAh + so);
        }
#pragma unroll
        for (int mf = 0; mf < 4; mf++)
#pragma unroll
            for (int nf = 0; nf < 4; nf++) {
                mma16816(acc[mf][nf], a[mf], bh[nf]);
                mma16816(acc[mf][nf], a[mf], bl[nf]);
            }
#pragma unroll
        for (int mf = 0; mf < 4; mf++) {
            int off = ((arow + (mf << 4)) << 7) + acol;
            int so = off ^ ((off >> 3) & 0x70);
            LDSM4(a[mf][0], a[mf][1], a[mf][2], a[mf][3], sAl + so);
        }
#pragma unroll
        for (int mf = 0; mf < 4; mf++)
#pragma unroll
            for (int nf = 0; nf < 4; nf++)
                mma16816(acc[mf][nf], a[mf], bh[nf]);
    }
}

// single-pass fp16 warp slab, B [k][n] trans (128B pitch) — context
__device__ __forceinline__ void warp_slab_h(
    u32 sA, u32 sB, int mwarp, int nwarp, int lane, float acc[4][4][4])
{
#pragma unroll
    for (int ks = 0; ks < 4; ks++) {
        const int k0 = ks << 4;
        u32 b[4][2], a[4][4];
#pragma unroll
        for (int nf = 0; nf < 2; nf++) {
            int kr = k0 + (lane & 15);
            int nc = nwarp + (nf << 4) + ((lane >> 4) << 3);
            int off = (kr << 7) + (nc << 1);
            int so = off ^ ((off >> 3) & 0x70);
            LDSM4T(b[nf*2][0], b[nf*2][1], b[nf*2+1][0], b[nf*2+1][1], sB + so);
        }
        int arow = mwarp + (lane & 15);
        int acol = (k0 + ((lane >> 4) << 3)) << 1;
#pragma unroll
        for (int mf = 0; mf < 4; mf++) {
            int off = ((arow + (mf << 4)) << 7) + acol;
            int so = off ^ ((off >> 3) & 0x70);
            LDSM4(a[mf][0], a[mf][1], a[mf][2], a[mf][3], sA + so);
        }
#pragma unroll
        for (int mf = 0; mf < 4; mf++)
#pragma unroll
            for (int nf = 0; nf < 4; nf++)
                mma16816h(acc[mf][nf], a[mf], b[nf]);
    }
}

// single-pass fp16 warp slab, B [k][n] trans (256B pitch) — out-projection
__device__ __forceinline__ void warp_slab_o(
    u32 sA, u32 sB, int mwarp, int nwarp, int lane, float acc[4][4][4])
{
#pragma unroll
    for (int ks = 0; ks < 4; ks++) {
        const int k0 = ks << 4;
        u32 b[4][2], a[4][4];
#pragma unroll
        for (int nf = 0; nf < 2; nf++) {
            int kr = k0 + (lane & 15);
            int nc = nwarp + (nf << 4) + ((lane >> 4) << 3);
            int off = (kr << 8) + (nc << 1);
            int so = off ^ ((off >> 4) & 0x70);
            LDSM4T(b[nf*2][0], b[nf*2][1], b[nf*2+1][0], b[nf*2+1][1], sB + so);
        }
        int arow = mwarp + (lane & 15);
        int acol = (k0 + ((lane >> 4) << 3)) << 1;
#pragma unroll
        for (int mf = 0; mf < 4; mf++) {
            int off = ((arow + (mf << 4)) << 7) + acol;
            int so = off ^ ((off >> 3) & 0x70);
            LDSM4(a[mf][0], a[mf][1], a[mf][2], a[mf][3], sA + so);
        }
#pragma unroll
        for (int mf = 0; mf < 4; mf++)
#pragma unroll
            for (int nf = 0; nf < 4; nf++)
                mma16816h(acc[mf][nf], a[mf], b[nf]);
    }
}

__device__ __forceinline__ void split_store2(bf16* H, bf16* L, float v0, float v1) {
    bf16 h0 = __float2bfloat16(v0), h1 = __float2bfloat16(v1);
    bf16 l0 = __float2bfloat16(v0 - __bfloat162float(h0));
    bf16 l1 = __float2bfloat16(v1 - __bfloat162float(h1));
    __nv_bfloat162 hp; hp.x = h0; hp.y = h1;
    __nv_bfloat162 lp; lp.x = l0; lp.y = l1;
    *(__nv_bfloat162*)H = hp;
    *(__nv_bfloat162*)L = lp;
}

__device__ __forceinline__ float fexp(float x) {
    x = fmaxf(x, -87.0f);
    float t = x * 1.4426950408889634f;
    int ei = __float2int_rn(t);
    float f = t - (float)ei;
    float p = 1.5403530e-4f;
    p = fmaf(p, f, 1.3333558e-3f);
    p = fmaf(p, f, 9.6181291e-3f);
    p = fmaf(p, f, 5.5504109e-2f);
    p = fmaf(p, f, 2.4022651e-1f);
    p = fmaf(p, f, 6.9314718e-1f);
    p = fmaf(p, f, 1.0f);
    return p * __int_as_float((ei + 127) << 23);
}

// ---------------- converters ------------------------------------------------
__global__ void __launch_bounds__(256) conv_x(
    const float* __restrict__ x, const float* __restrict__ dr,
    bf16* xh, bf16* xl, bf16* xsh, bf16* xsl)
{
    int i0 = blockIdx.x * 1024 + threadIdx.x;
#pragma unroll
    for (int k = 0; k < 4; k++) {
        int i = i0 + k * 256;
        float v = x[i];
        float d = dr[i >> 10];
        bf16 h = __float2bfloat16(v);
        xh[i] = h; xl[i] = __float2bfloat16(v - __bfloat162float(h));
        float vs = v * d;
        bf16 hs = __float2bfloat16(vs);
        xsh[i] = hs; xsl[i] = __float2bfloat16(vs - __bfloat162float(hs));
    }
}

__global__ void __launch_bounds__(256) conv_w4(
    const float* __restrict__ Wq, const float* __restrict__ Wk,
    const float* __restrict__ Wv, const float* __restrict__ Wo,
    bf16* __restrict__ H, bf16* __restrict__ L, __half* __restrict__ W16)
{
    int sel = blockIdx.y;
    const float* W = sel == 0 ? Wq : (sel == 1 ? Wk : (sel == 2 ? Wv : Wo));
    size_t base = (size_t)sel * DD * DD;
    int i0 = blockIdx.x * 1024 + threadIdx.x;
#pragma unroll
    for (int k = 0; k < 4; k++) {
        int i = i0 + k * 256;
        float v = W[i];
        if (sel == 3) {
            W16[i] = __float2half(v);
        } else {
            bf16 h = __float2bfloat16(v);
            H[base + i] = h;
            L[base + i] = __float2bfloat16(v - __bfloat162float(h));
        }
    }
}

// ---------------- 3-stage pipelined 128x128 GEMM mainloop (16 slabs) -------
#define PG_A   0
#define PG_AL  16384
#define PG_B   32768
#define PG_BL  49152
#define PG_STAGE 65536
#define PG_SMEM  (3 * PG_STAGE)

__device__ __forceinline__ void proj_issue(u32 st,
    const bf16* __restrict__ Ah, const bf16* __restrict__ Al,
    const bf16* __restrict__ Bh, const bf16* __restrict__ Bl, int s)
{
    issue_A128(st + PG_A,  Ah + s * 64, DD);
    issue_A128(st + PG_AL, Al + s * 64, DD);
    issue_B256(st + PG_B,  Bh + (size_t)s * 64 * DD, DD);
    issue_B256(st + PG_BL, Bl + (size_t)s * 64 * DD, DD);
    CPCOMMIT();
}

__device__ __forceinline__ void proj_mainloop(u32 sb,
    const bf16* __restrict__ Ah, const bf16* __restrict__ Al,
    const bf16* __restrict__ Bh, const bf16* __restrict__ Bl,
    int lane, int mwarp, int nwarp, float acc[4][4][4])
{
    proj_issue(sb + 0 * PG_STAGE, Ah, Al, Bh, Bl, 0);
    proj_issue(sb + 1 * PG_STAGE, Ah, Al, Bh, Bl, 1);
    for (int s = 0; s < 16; s++) {
        if (s < 15) { CPWAIT(1); } else { CPWAIT(0); }
        __syncthreads();
        if (s + 2 < 16)
            proj_issue(sb + ((s + 2) % 3) * PG_STAGE, Ah, Al, Bh, Bl, s + 2);
        u32 cur = sb + (s % 3) * PG_STAGE;
        warp_slab<4, 0, 256>(cur + PG_A, cur + PG_AL, cur + PG_B, cur + PG_BL,
                             mwarp, nwarp, lane, acc);
    }
}

// fused QKV projection
__global__ void __launch_bounds__(256) k_proj_qkv(
    const bf16* __restrict__ xh, const bf16* __restrict__ xl,
    const bf16* __restrict__ xsh, const bf16* __restrict__ xsl,
    const bf16* __restrict__ Whi, const bf16* __restrict__ Wlo,
    const float* __restrict__ bq, const float* __restrict__ bk,
    const float* __restrict__ bv,
    bf16* __restrict__ Qh, bf16* __restrict__ Ql,
    bf16* __restrict__ Kh, bf16* __restrict__ Kl,
    __half* __restrict__ Vp)
{
    extern __shared__ char sm[];
    u32 sb = smem_u32(sm);
    int ng = blockIdx.x << 7;
    int sel = ng >> 10, ncol = ng & 1023;
    int m0 = blockIdx.y << 7;
    int lane = threadIdx.x & 31, wid = threadIdx.x >> 5;
    int mwarp = (wid >> 2) << 6, nwarp = (wid & 3) << 5;

    const bf16* Ah = (sel == 2 ? xsh : xh) + (size_t)m0 * DD;
    const bf16* Al = (sel == 2 ? xsl : xl) + (size_t)m0 * DD;
    const bf16* Bh = Whi + (size_t)sel * DD * DD + ncol;
    const bf16* Bl = Wlo + (size_t)sel * DD * DD + ncol;
    const float* bias = sel == 0 ? bq : (sel == 1 ? bk : bv);
    bf16* Ohi = sel == 0 ? Qh : Kh;
    bf16* Olo = sel == 0 ? Ql : Kl;

    float acc[4][4][4];
#pragma unroll
    for (int i = 0; i < 4; i++)
#pragma unroll
        for (int j = 0; j < 4; j++)
#pragma unroll
            for (int k = 0; k < 4; k++) acc[i][j][k] = 0.0f;

    proj_mainloop(sb, Ah, Al, Bh, Bl, lane, mwarp, nwarp, acc);

    int g = lane >> 2, t = (lane & 3) << 1;
#pragma unroll
    for (int mf = 0; mf < 4; mf++)
#pragma unroll
        for (int half = 0; half < 2; half++) {
            int r = m0 + mwarp + (mf << 4) + g + (half << 3);
#pragma unroll
            for (int nf = 0; nf < 4; nf++) {
                int n = ncol + nwarp + (nf << 3) + t;
                float v0 = acc[mf][nf][half * 2 + 0] + bias[n];
                float v1 = acc[mf][nf][half * 2 + 1] + bias[n + 1];
                if (sel == 2) {
                    *(__half2*)(Vp + (size_t)r * DD + n) = __floats2half2_rn(v0, v1);
                } else {
                    split_store2(Ohi + (size_t)r * DD + n, Olo + (size_t)r * DD + n, v0, v1);
                }
            }
        }
}

// ---------------- scores + tile-local softmax stats -> e fp16 ---------------
#define S_AHI 0
#define S_ALO 16384
#define S_BHI 32768
#define S_BLO 49152
#define S_RELB 65536
#define S_RED  66560
#define S_SMEM 68608

__global__ void __launch_bounds__(256) k_scores_e(
    const bf16* __restrict__ Qh, const bf16* __restrict__ Ql,
    const bf16* __restrict__ Kh, const bf16* __restrict__ Kl,
    const float* __restrict__ delta, __half* __restrict__ P,
    float* __restrict__ Tm, float* __restrict__ Ts)
{
    extern __shared__ char sm[];
    u32 sb = smem_u32(sm);
    int z = blockIdx.z, b = z >> 4, h = z & 15;
    int m0 = blockIdx.y << 7, n0 = blockIdx.x << 7;
    int lane = threadIdx.x & 31, wid = threadIdx.x >> 5;
    int mwarp = (wid >> 2) << 6, nwarp = (wid & 3) << 5;

    size_t qoff = (size_t)(b * LL + m0) * DD + h * DK;
    size_t koff = (size_t)(b * LL + n0) * DD + h * DK;
    issue_A128(sb + S_AHI, Qh + qoff, DD);
    issue_A128(sb + S_ALO, Ql + qoff, DD);
    issue_A128(sb + S_BHI, Kh + koff, DD);
    issue_A128(sb + S_BLO, Kl + koff, DD);
    CPCOMMIT();

    float* relb = (float*)(sm + S_RELB);
    if (threadIdx.x < 128)
        relb[threadIdx.x] = logf(delta[b * LL + n0 + threadIdx.x] + 1e-6f);

    float acc[4][4][4];
#pragma unroll
    for (int i = 0; i < 4; i++)
#pragma unroll
        for (int j = 0; j < 4; j++)
#pragma unroll
            for (int k = 0; k < 4; k++) acc[i][j][k] = 0.0f;

    CPWAIT(0);
    __syncthreads();
    warp_slab<3, 1, 128>(sb + S_AHI, sb + S_ALO, sb + S_BHI, sb + S_BLO,
                         mwarp, nwarp, lane, acc);

    int g = lane >> 2, tq = lane & 3;
    float* red = (float*)(sm + S_RED);

    // bias transform
#pragma unroll
    for (int mf = 0; mf < 4; mf++)
#pragma unroll
        for (int half = 0; half < 2; half++) {
            int m = m0 + mwarp + (mf << 4) + g + (half << 3);
#pragma unroll
            for (int nf = 0; nf < 4; nf++) {
                int nl = nwarp + (nf << 3) + (tq << 1);
                int n = n0 + nl;
                acc[mf][nf][half*2+0] = acc[mf][nf][half*2+0] * 0.125f
                    - 0.1f * fabsf((float)(m - n)) + relb[nl];
                acc[mf][nf][half*2+1] = acc[mf][nf][half*2+1] * 0.125f
                    - 0.1f * fabsf((float)(m - n - 1)) + relb[nl + 1];
            }
        }

    // tile-local row max across the 4 n-warps
#pragma unroll
    for (int mf = 0; mf < 4; mf++)
#pragma unroll
        for (int half = 0; half < 2; half++) {
            float mx = -1e30f;
#pragma unroll
            for (int nf = 0; nf < 4; nf++)
                mx = fmaxf(mx, fmaxf(acc[mf][nf][half*2], acc[mf][nf][half*2+1]));
            mx = fmaxf(mx, __shfl_xor_sync(0xffffffffu, mx, 1));
            mx = fmaxf(mx, __shfl_xor_sync(0xffffffffu, mx, 2));
            if (tq == 0)
                red[(wid & 3) * 128 + mwarp + (mf << 4) + g + (half << 3)] = mx;
        }
    __syncthreads();
    float mrow[4][2];
#pragma unroll
    for (int mf = 0; mf < 4; mf++)
#pragma unroll
        for (int half = 0; half < 2; half++) {
            int r = mwarp + (mf << 4) + g + (half << 3);
            mrow[mf][half] = fmaxf(fmaxf(red[r], red[128 + r]),
                                   fmaxf(red[256 + r], red[384 + r]));
        }
    __syncthreads();

    // e = exp(s - m_tile) + row sums
#pragma unroll
    for (int mf = 0; mf < 4; mf++)
#pragma unroll
        for (int half = 0; half < 2; half++) {
            float s = 0.0f;
#pragma unroll
            for (int nf = 0; nf < 4; nf++) {
                float e0 = fexp(acc[mf][nf][half*2]   - mrow[mf][half]);
                float e1 = fexp(acc[mf][nf][half*2+1] - mrow[mf][half]);
                acc[mf][nf][half*2]   = e0;
                acc[mf][nf][half*2+1] = e1;
                s += e0 + e1;
            }
            s += __shfl_xor_sync(0xffffffffu, s, 1);
            s += __shfl_xor_sync(0xffffffffu, s, 2);
            if (tq == 0)
                red[(wid & 3) * 128 + mwarp + (mf << 4) + g + (half << 3)] = s;
        }
    __syncthreads();

    if ((wid & 3) == 0 && tq == 0) {
#pragma unroll
        for (int mf = 0; mf < 4; mf++)
#pragma unroll
            for (int half = 0; half < 2; half++) {
                int r = mwarp + (mf << 4) + g + (half << 3);
                float tot = red[r] + red[128 + r] + red[256 + r] + red[384 + r];
                size_t sb2 = ((size_t)z * 16 + blockIdx.x) * 2048 + m0 + r;
                Tm[sb2] = mrow[mf][half];
                Ts[sb2] = tot;
            }
    }

    // write e (fp16) into P buffer
#pragma unroll
    for (int mf = 0; mf < 4; mf++)
#pragma unroll
        for (int half = 0; half < 2; half++) {
            int r = mwarp + (mf << 4) + g + (half << 3);
            __half* erow = P + ((size_t)z * LL + m0 + r) * LL + n0;
#pragma unroll
            for (int nf = 0; nf < 4; nf++) {
                int nl = nwarp + (nf << 3) + (tq << 1);
                *(__half2*)(erow + nl) =
                    __floats2half2_rn(acc[mf][nf][half*2], acc[mf][nf][half*2+1]);
            }
        }
}

// ---------------- correction: P = e * exp(m_t - M)/Z (in place) + mean -----
__global__ void __launch_bounds__(256) k_corr(
    __half* __restrict__ P, const float* __restrict__ Tm,
    const float* __restrict__ Ts, float* __restrict__ outm)
{
    int bq = blockIdx.x;
    int b = bq >> 11, q = bq & 2047;
    int tid = threadIdx.x;
    __shared__ float smm[256], sms[256], smM[16], smZ[16], smc[256];
    int h = tid >> 4, tt = tid & 15;
    size_t stb = ((size_t)(b * 16 + h) * 16 + tt) * 2048 + q;
    smm[tid] = Tm[stb];
    sms[tid] = Ts[stb];
    __syncthreads();
    if (tid < 16) {
        float M = -1e30f;
#pragma unroll
        for (int j = 0; j < 16; j++) M = fmaxf(M, smm[tid * 16 + j]);
        float Z = 0.0f;
#pragma unroll
        for (int j = 0; j < 16; j++) Z += sms[tid * 16 + j] * fexp(smm[tid * 16 + j] - M);
        smM[tid] = M;
        smZ[tid] = Z;
    }
    __syncthreads();
    smc[tid] = fexp(smm[tid] - smM[h]) / smZ[h];
    __syncthreads();

    float acc[8];
#pragma unroll
    for (int j = 0; j < 8; j++) acc[j] = 0.0f;
    int col = tid << 3;
    int tile = tid >> 4;
    for (int hh = 0; hh < HH; hh++) {
        __half* row = P + ((size_t)(b * HH + hh) * LL + q) * LL;
        union { uint4 u; __half2 hp[4]; } v;
        v.u = *(uint4*)(row + col);
        float sc = smc[hh * 16 + tile];
#pragma unroll
        for (int j = 0; j < 4; j++) {
            float2 f = __half22float2(v.hp[j]);
            f.x *= sc; f.y *= sc;
            acc[j * 2]     += f.x;
            acc[j * 2 + 1] += f.y;
            v.hp[j] = __floats2half2_rn(f.x, f.y);
        }
        *(uint4*)(row + col) = v.u;
    }
    if (outm) {
        float* o = outm + (size_t)bq * LL + col;
        float4 o0, o1;
        o0.x = acc[0] * 0.0625f; o0.y = acc[1] * 0.0625f;
        o0.z = acc[2] * 0.0625f; o0.w = acc[3] * 0.0625f;
        o1.x = acc[4] * 0.0625f; o1.y = acc[5] * 0.0625f;
        o1.z = acc[6] * 0.0625f; o1.w = acc[7] * 0.0625f;
        *(float4*)o       = o0;
        *(float4*)(o + 4) = o1;
    }
}

// ---------------- context: ctx = P @ V (fp16 1-pass) -> C fp16 --------------
#define C_A   0
#define C_B   32768
#define C_STAGE 40960
#define C_SMEM  81920

__device__ __forceinline__ void ctx_issue(u32 st, const __half* Pb,
                                          const __half* Vb, int s)
{
    issue_A256(st + C_A, (const bf16*)(Pb + s * 64), LL);
    issue_B64 (st + C_B, (const bf16*)(Vb + (size_t)s * 64 * DD), DD);
    CPCOMMIT();
}

__global__ void __launch_bounds__(256) k_context(
    const __half* __restrict__ P, const __half* __restrict__ V,
    __half* __restrict__ C16)
{
    extern __shared__ char sm[];
    u32 sb = smem_u32(sm);
    int z = blockIdx.y, b = z >> 4, h = z & 15;
    int m0 = blockIdx.x << 8;
    int lane = threadIdx.x & 31, wid = threadIdx.x >> 5;
    int mwarp = (wid >> 1) << 6, nwarp = (wid & 1) << 5;

    float acc[4][4][4];
#pragma unroll
    for (int i = 0; i < 4; i++)
#pragma unroll
        for (int j = 0; j < 4; j++)
#pragma unroll
            for (int k = 0; k < 4; k++) acc[i][j][k] = 0.0f;

    const __half* Pb = P + (size_t)z * LL * LL + (size_t)m0 * LL;
    const __half* Vb = V + (size_t)b * LL * DD + h * DK;

    ctx_issue(sb, Pb, Vb, 0);
    for (int s = 0; s < LL / 64; s++) {
        CPWAIT(0);
        __syncthreads();
        if (s + 1 < LL / 64)
            ctx_issue(sb + ((s + 1) & 1) * C_STAGE, Pb, Vb, s + 1);
        u32 cur = sb + (s & 1) * C_STAGE;
        warp_slab_h(cur + C_A, cur + C_B, mwarp, nwarp, lane, acc);
    }

    int g = lane >> 2, t = (lane & 3) << 1;
#pragma unroll
    for (int mf = 0; mf < 4; mf++)
#pragma unroll
        for (int half = 0; half < 2; half++) {
            int r = m0 + mwarp + (mf << 4) + g + (half << 3);
            size_t rb = (size_t)(b * LL + r) * DD + h * DK;
#pragma unroll
            for (int nf = 0; nf < 4; nf++) {
                int n = nwarp + (nf << 3) + t;
                *(__half2*)(C16 + rb + n) =
                    __floats2half2_rn(acc[mf][nf][half*2], acc[mf][nf][half*2+1]);
            }
        }
}

// ---------------- out projection: fp16 1-pass, fp32 out + bias --------------
#define PO_A 0
#define PO_B 16384
#define PO_STAGE 32768
#define PO_SMEM  98304

__device__ __forceinline__ void po_issue(u32 st, const __half* A,
                                         const __half* W, int s)
{
    issue_A128(st + PO_A, (const bf16*)(A + s * 64), DD);
    issue_B256(st + PO_B, (const bf16*)(W + (size_t)s * 64 * DD), DD);
    CPCOMMIT();
}

__global__ void __launch_bounds__(256) k_proj_o(
    const __half* __restrict__ C16, const __half* __restrict__ W16,
    const float* __restrict__ bias, float* __restrict__ Of)
{
    extern __shared__ char sm[];
    u32 sb = smem_u32(sm);
    int n0 = blockIdx.x << 7, m0 = blockIdx.y << 7;
    int lane = threadIdx.x & 31, wid = threadIdx.x >> 5;
    int mwarp = (wid >> 2) << 6, nwarp = (wid & 3) << 5;

    float acc[4][4][4];
#pragma unroll
    for (int i = 0; i < 4; i++)
#pragma unroll
        for (int j = 0; j < 4; j++)
#pragma unroll
            for (int k = 0; k < 4; k++) acc[i][j][k] = 0.0f;

    const __half* A = C16 + (size_t)m0 * DD;
    const __half* W = W16 + n0;

    po_issue(sb + 0 * PO_STAGE, A, W, 0);
    po_issue(sb + 1 * PO_STAGE, A, W, 1);
    for (int s = 0; s < 16; s++) {
        if (s < 15) { CPWAIT(1); } else { CPWAIT(0); }
        __syncthreads();
        if (s + 2 < 16)
            po_issue(sb + ((s + 2) % 3) * PO_STAGE, A, W, s + 2);
        u32 cur = sb + (s % 3) * PO_STAGE;
        warp_slab_o(cur + PO_A, cur + PO_B, mwarp, nwarp, lane, acc);
    }

    int g = lane >> 2, t = (lane & 3) << 1;
#pragma unroll
    for (int mf = 0; mf < 4; mf++)
#pragma unroll
        for (int half = 0; half < 2; half++) {
            int r = m0 + mwarp + (mf << 4) + g + (half << 3);
#pragma unroll
            for (int nf = 0; nf < 4; nf++) {
                int n = n0 + nwarp + (nf << 3) + t;
                float2 o;
                o.x = acc[mf][nf][half * 2 + 0] + bias[n];
                o.y = acc[mf][nf][half * 2 + 1] + bias[n + 1];
                *(float2*)(Of + (size_t)r * DD + n) = o;
            }
        }
}

// ---------------- launch ----------------------------------------------------
extern "C" void kernel_launch(void* const* d_in, const int* in_sizes, int n_in,
                              void* d_out, int out_size)
{
    const float* x   = (const float*)d_in[0];
    const float* dr  = (const float*)d_in[1];
    const float* Wq  = (const float*)d_in[2];
    const float* bq  = (const float*)d_in[3];
    const float* Wk  = (const float*)d_in[4];
    const float* bk  = (const float*)d_in[5];
    const float* Wv  = (const float*)d_in[6];
    const float* bv  = (const float*)d_in[7];
    const float* Wo  = (const float*)d_in[8];
    const float* bo  = (const float*)d_in[9];
    float* out = (float*)d_out;

    __half *pP, *pV, *pC16, *pWo16;
    float *pTm, *pTs;
    bf16 *pxhi, *pxlo, *pxshi, *pxslo, *pWhi, *pWlo;
    bf16 *pQhi, *pQlo, *pKhi, *pKlo;
    cudaGetSymbolAddress((void**)&pP,    g_P);
    cudaGetSymbolAddress((void**)&pV,    g_V);
    cudaGetSymbolAddress((void**)&pC16,  g_C16);
    cudaGetSymbolAddress((void**)&pWo16, g_Wo16);
    cudaGetSymbolAddress((void**)&pTm,   g_Tm);
    cudaGetSymbolAddress((void**)&pTs,   g_Ts);
    cudaGetSymbolAddress((void**)&pxhi,  g_xhi);
    cudaGetSymbolAddress((void**)&pxlo,  g_xlo);
    cudaGetSymbolAddress((void**)&pxshi, g_xshi);
    cudaGetSymbolAddress((void**)&pxslo, g_xslo);
    cudaGetSymbolAddress((void**)&pWhi,  g_Whi);
    cudaGetSymbolAddress((void**)&pWlo,  g_Wlo);
    cudaGetSymbolAddress((void**)&pQhi,  g_Qhi);
    cudaGetSymbolAddress((void**)&pQlo,  g_Qlo);
    cudaGetSymbolAddress((void**)&pKhi,  g_Khi);
    cudaGetSymbolAddress((void**)&pKlo,  g_Klo);

    cudaFuncSetAttribute(k_proj_qkv, cudaFuncAttributeMaxDynamicSharedMemorySize, PG_SMEM);
    cudaFuncSetAttribute(k_proj_o,   cudaFuncAttributeMaxDynamicSharedMemorySize, PO_SMEM);
    cudaFuncSetAttribute(k_scores_e, cudaFuncAttributeMaxDynamicSharedMemorySize, S_SMEM);
    cudaFuncSetAttribute(k_context,  cudaFuncAttributeMaxDynamicSharedMemorySize, C_SMEM);

    // converters
    conv_x<<<BL, 256>>>(x, dr, pxhi, pxlo, pxshi, pxslo);
    dim3 gw(1024, 4);
    conv_w4<<<gw, 256>>>(Wq, Wk, Wv, Wo, pWhi, pWlo, pWo16);

    // fused QKV projection (3-stage pipelined HMMA)
    dim3 gqkv(3 * DD / 128, BL / 128);   // (24, 32)
    k_proj_qkv<<<gqkv, 256, PG_SMEM>>>(pxhi, pxlo, pxshi, pxslo, pWhi, pWlo,
                                       bq, bk, bv,
                                       pQhi, pQlo, pKhi, pKlo, pV);

    // scores -> e fp16 + tile stats (no S buffer)
    dim3 gsc(LL / 128, LL / 128, BB * HH);   // (16, 16, 32)
    k_scores_e<<<gsc, 256, S_SMEM>>>(pQhi, pQlo, pKhi, pKlo, dr, pP, pTm, pTs);

    // correction (normalize in place) + head-mean
    bool write_mean = (out_size >= (BL * DD + BB * LL * LL));
    k_corr<<<BL, 256>>>(pP, pTm, pTs,
                        write_mean ? out + (size_t)BL * DD : nullptr);

    // context (fp16 single-pass) -> C fp16
    dim3 gctx(LL / 256, BB * HH);        // (8, 32)
    k_context<<<gctx, 256, C_SMEM>>>(pP, pV, pC16);

    // output projection (fp16 1-pass, fp32 out + bias)
    dim3 go(DD / 128, BL / 128);         // (8, 32)
    k_proj_o<<<go, 256, PO_SMEM>>>(pC16, pWo16, bo, out);
}

// round 14
// speedup vs baseline: 1.1169x; 1.1169x over previous
#include <cuda_runtime.h>
#include <cuda_bf16.h>
#include <cuda_fp16.h>
#include <math.h>
#include <stdint.h>

#define BB 2
#define LL 2048
#define DD 1024
#define HH 16
#define DK 64
#define BL (BB*LL)              // 4096

typedef unsigned int u32;
typedef __nv_bfloat16 bf16;

// ---------------- scratch (device globals; no allocation allowed) ----------
__device__ float  g_S[(size_t)BB*HH*LL*LL];      // 512 MB raw scores
__device__ __half g_P[(size_t)BB*HH*LL*LL];      // 256 MB probs fp16
__device__ bf16   g_xhi [BL*DD], g_xlo [BL*DD];
__device__ __half g_xs16[BL*DD];                 // (x*delta) fp16
__device__ bf16   g_Whi[2*DD*DD], g_Wlo[2*DD*DD]; // Wq/Wk hi/lo [k][n]
__device__ __half g_Wv16[DD*DD];                 // Wv fp16
__device__ __half g_Wo16[DD*DD];                 // Wo fp16
__device__ bf16   g_Qhi[BL*DD], g_Qlo[BL*DD];
__device__ bf16   g_Khi[BL*DD], g_Klo[BL*DD];
__device__ __half g_V[BL*DD];                    // V fp16
__device__ __half g_C16[BL*DD];                  // context fp16

// ---------------- ptx helpers ----------------------------------------------
__device__ __forceinline__ u32 smem_u32(const void* p) {
    u32 a;
    asm("{ .reg .u64 t; cvta.to.shared.u64 t, %1; cvt.u32.u64 %0, t; }"
        : "=r"(a) : "l"(p));
    return a;
}

#define LDSM4(R0,R1,R2,R3,ADDR) \
    asm volatile("ldmatrix.sync.aligned.m8n8.x4.shared.b16 {%0,%1,%2,%3}, [%4];" \
        : "=r"(R0),"=r"(R1),"=r"(R2),"=r"(R3) : "r"(ADDR))
#define LDSM4T(R0,R1,R2,R3,ADDR) \
    asm volatile("ldmatrix.sync.aligned.m8n8.x4.trans.shared.b16 {%0,%1,%2,%3}, [%4];" \
        : "=r"(R0),"=r"(R1),"=r"(R2),"=r"(R3) : "r"(ADDR))

__device__ __forceinline__ void mma16816(float* c, const u32* a, const u32* b) {
    asm volatile(
        "mma.sync.aligned.m16n8k16.row.col.f32.bf16.bf16.f32 "
        "{%0,%1,%2,%3}, {%4,%5,%6,%7}, {%8,%9}, {%0,%1,%2,%3};"
        : "+f"(c[0]), "+f"(c[1]), "+f"(c[2]), "+f"(c[3])
        : "r"(a[0]), "r"(a[1]), "r"(a[2]), "r"(a[3]), "r"(b[0]), "r"(b[1]));
}

__device__ __forceinline__ void mma16816h(float* c, const u32* a, const u32* b) {
    asm volatile(
        "mma.sync.aligned.m16n8k16.row.col.f32.f16.f16.f32 "
        "{%0,%1,%2,%3}, {%4,%5,%6,%7}, {%8,%9}, {%0,%1,%2,%3};"
        : "+f"(c[0]), "+f"(c[1]), "+f"(c[2]), "+f"(c[3])
        : "r"(a[0]), "r"(a[1]), "r"(a[2]), "r"(a[3]), "r"(b[0]), "r"(b[1]));
}

#define CPA16(dst, src) \
    asm volatile("cp.async.cg.shared.global [%0], [%1], 16;" :: "r"(dst), "l"(src))
#define CPCOMMIT() asm volatile("cp.async.commit_group;" ::: "memory")
#define CPWAIT(n)  asm volatile("cp.async.wait_group %0;" :: "n"(n) : "memory")

// ---------------- async staging (swizzled) ----------------------------------
__device__ __forceinline__ void issue_A128(u32 dst, const bf16* A, size_t lda) {
#pragma unroll
    for (int i = 0; i < 4; i++) {
        int idx = threadIdx.x + (i << 8);
        int r = idx >> 3, c = idx & 7;
        int off = (r << 7) | (c << 4);
        CPA16(dst + (off ^ ((off >> 3) & 0x70)), A + (size_t)r * lda + (c << 3));
    }
}
__device__ __forceinline__ void issue_A256(u32 dst, const bf16* A, size_t lda) {
#pragma unroll
    for (int i = 0; i < 8; i++) {
        int idx = threadIdx.x + (i << 8);
        int r = idx >> 3, c = idx & 7;
        int off = (r << 7) | (c << 4);
        CPA16(dst + (off ^ ((off >> 3) & 0x70)), A + (size_t)r * lda + (c << 3));
    }
}
__device__ __forceinline__ void issue_B256(u32 dst, const bf16* B, size_t ldb) {
#pragma unroll
    for (int i = 0; i < 4; i++) {
        int idx = threadIdx.x + (i << 8);
        int r = idx >> 4, c = idx & 15;
        int off = (r << 8) | (c << 4);
        CPA16(dst + (off ^ ((off >> 4) & 0x70)), B + (size_t)r * ldb + (c << 3));
    }
}
__device__ __forceinline__ void issue_B64(u32 dst, const bf16* B, size_t ldb) {
#pragma unroll
    for (int i = 0; i < 2; i++) {
        int idx = threadIdx.x + (i << 8);
        int r = idx >> 3, c = idx & 7;
        int off = (r << 7) | (c << 4);
        CPA16(dst + (off ^ ((off >> 3) & 0x70)), B + (size_t)r * ldb + (c << 3));
    }
}

// ---------------- warp slab: 64x32 warp tile, 3-pass bf16 hi/lo ------------
template<int SW, int BMODE, int BPITCH>
__device__ __forceinline__ void warp_slab(
    u32 sAh, u32 sAl, u32 sBh, u32 sBl,
    int mwarp, int nwarp, int lane, float acc[4][4][4])
{
#pragma unroll
    for (int ks = 0; ks < 4; ks++) {
        const int k0 = ks << 4;
        u32 bh[4][2], bl[4][2], a[4][4];
#pragma unroll
        for (int nf = 0; nf < 2; nf++) {
            int off;
            if (BMODE == 0) {
                int kr = k0 + (lane & 15);
                int nc = nwarp + (nf << 4) + ((lane >> 4) << 3);
                off = kr * BPITCH + (nc << 1);
            } else {
                int nr = nwarp + (nf << 4) + (lane & 7) + ((lane >> 4) << 3);
                int kc = k0 + (((lane >> 3) & 1) << 3);
                off = (nr << 7) + (kc << 1);
            }
            int so = off ^ ((off >> SW) & 0x70);
            if (BMODE == 0) {
                LDSM4T(bh[nf*2][0], bh[nf*2][1], bh[nf*2+1][0], bh[nf*2+1][1], sBh + so);
                LDSM4T(bl[nf*2][0], bl[nf*2][1], bl[nf*2+1][0], bl[nf*2+1][1], sBl + so);
            } else {
                LDSM4(bh[nf*2][0], bh[nf*2][1], bh[nf*2+1][0], bh[nf*2+1][1], sBh + so);
                LDSM4(bl[nf*2][0], bl[nf*2][1], bl[nf*2+1][0], bl[nf*2+1][1], sBl + so);
            }
        }
        int arow = mwarp + (lane & 15);
        int acol = (k0 + ((lane >> 4) << 3)) << 1;
#pragma unroll
        for (int mf = 0; mf < 4; mf++) {
            int off = ((arow + (mf << 4)) << 7) + acol;
            int so = off ^ ((off >> 3) & 0x70);
            LDSM4(a[mf][0], a[mf][1], a[mf][2], a[mf][3], sAh + so);
        }
#pragma unroll
        for (int mf = 0; mf < 4; mf++)
#pragma unroll
            for (int nf = 0; nf < 4; nf++) {
                mma16816(acc[mf][nf], a[mf], bh[nf]);
                mma16816(acc[mf][nf], a[mf], bl[nf]);
            }
#pragma unroll
        for (int mf = 0; mf < 4; mf++) {
            int off = ((arow + (mf << 4)) << 7) + acol;
            int so = off ^ ((off >> 3) & 0x70);
            LDSM4(a[mf][0], a[mf][1], a[mf][2], a[mf][3], sAl + so);
        }
#pragma unroll
        for (int mf = 0; mf < 4; mf++)
#pragma unroll
            for (int nf = 0; nf < 4; nf++)
                mma16816(acc[mf][nf], a[mf], bh[nf]);
    }
}

// single-pass fp16 warp slab, B [k][n] trans (128B pitch) — context
__device__ __forceinline__ void warp_slab_h(
    u32 sA, u32 sB, int mwarp, int nwarp, int lane, float acc[4][4][4])
{
#pragma unroll
    for (int ks = 0; ks < 4; ks++) {
        const int k0 = ks << 4;
        u32 b[4][2], a[4][4];
#pragma unroll
        for (int nf = 0; nf < 2; nf++) {
            int kr = k0 + (lane & 15);
            int nc = nwarp + (nf << 4) + ((lane >> 4) << 3);
            int off = (kr << 7) + (nc << 1);
            int so = off ^ ((off >> 3) & 0x70);
            LDSM4T(b[nf*2][0], b[nf*2][1], b[nf*2+1][0], b[nf*2+1][1], sB + so);
        }
        int arow = mwarp + (lane & 15);
        int acol = (k0 + ((lane >> 4) << 3)) << 1;
#pragma unroll
        for (int mf = 0; mf < 4; mf++) {
            int off = ((arow + (mf << 4)) << 7) + acol;
            int so = off ^ ((off >> 3) & 0x70);
            LDSM4(a[mf][0], a[mf][1], a[mf][2], a[mf][3], sA + so);
        }
#pragma unroll
        for (int mf = 0; mf < 4; mf++)
#pragma unroll
            for (int nf = 0; nf < 4; nf++)
                mma16816h(acc[mf][nf], a[mf], b[nf]);
    }
}

// single-pass fp16 warp slab, B [k][n] trans (256B pitch) — fp16 projections
__device__ __forceinline__ void warp_slab_o(
    u32 sA, u32 sB, int mwarp, int nwarp, int lane, float acc[4][4][4])
{
#pragma unroll
    for (int ks = 0; ks < 4; ks++) {
        const int k0 = ks << 4;
        u32 b[4][2], a[4][4];
#pragma unroll
        for (int nf = 0; nf < 2; nf++) {
            int kr = k0 + (lane & 15);
            int nc = nwarp + (nf << 4) + ((lane >> 4) << 3);
            int off = (kr << 8) + (nc << 1);
            int so = off ^ ((off >> 4) & 0x70);
            LDSM4T(b[nf*2][0], b[nf*2][1], b[nf*2+1][0], b[nf*2+1][1], sB + so);
        }
        int arow = mwarp + (lane & 15);
        int acol = (k0 + ((lane >> 4) << 3)) << 1;
#pragma unroll
        for (int mf = 0; mf < 4; mf++) {
            int off = ((arow + (mf << 4)) << 7) + acol;
            int so = off ^ ((off >> 3) & 0x70);
            LDSM4(a[mf][0], a[mf][1], a[mf][2], a[mf][3], sA + so);
        }
#pragma unroll
        for (int mf = 0; mf < 4; mf++)
#pragma unroll
            for (int nf = 0; nf < 4; nf++)
                mma16816h(acc[mf][nf], a[mf], b[nf]);
    }
}

__device__ __forceinline__ void split_store2(bf16* H, bf16* L, float v0, float v1) {
    bf16 h0 = __float2bfloat16(v0), h1 = __float2bfloat16(v1);
    bf16 l0 = __float2bfloat16(v0 - __bfloat162float(h0));
    bf16 l1 = __float2bfloat16(v1 - __bfloat162float(h1));
    __nv_bfloat162 hp; hp.x = h0; hp.y = h1;
    __nv_bfloat162 lp; lp.x = l0; lp.y = l1;
    *(__nv_bfloat162*)H = hp;
    *(__nv_bfloat162*)L = lp;
}

__device__ __forceinline__ float fexp(float x) {
    x = fmaxf(x, -87.0f);
    float t = x * 1.4426950408889634f;
    int ei = __float2int_rn(t);
    float f = t - (float)ei;
    float p = 1.5403530e-4f;
    p = fmaf(p, f, 1.3333558e-3f);
    p = fmaf(p, f, 9.6181291e-3f);
    p = fmaf(p, f, 5.5504109e-2f);
    p = fmaf(p, f, 2.4022651e-1f);
    p = fmaf(p, f, 6.9314718e-1f);
    p = fmaf(p, f, 1.0f);
    return p * __int_as_float((ei + 127) << 23);
}

// ---------------- converters ------------------------------------------------
__global__ void __launch_bounds__(256) conv_x(
    const float* __restrict__ x, const float* __restrict__ dr,
    bf16* xh, bf16* xl, __half* xs16)
{
    int i0 = blockIdx.x * 1024 + threadIdx.x;
#pragma unroll
    for (int k = 0; k < 4; k++) {
        int i = i0 + k * 256;
        float v = x[i];
        float d = dr[i >> 10];
        bf16 h = __float2bfloat16(v);
        xh[i] = h; xl[i] = __float2bfloat16(v - __bfloat162float(h));
        xs16[i] = __float2half(v * d);
    }
}

__global__ void __launch_bounds__(256) conv_w4(
    const float* __restrict__ Wq, const float* __restrict__ Wk,
    const float* __restrict__ Wv, const float* __restrict__ Wo,
    bf16* __restrict__ H, bf16* __restrict__ L,
    __half* __restrict__ Wv16, __half* __restrict__ Wo16)
{
    int sel = blockIdx.y;
    const float* W = sel == 0 ? Wq : (sel == 1 ? Wk : (sel == 2 ? Wv : Wo));
    size_t base = (size_t)sel * DD * DD;
    int i0 = blockIdx.x * 1024 + threadIdx.x;
#pragma unroll
    for (int k = 0; k < 4; k++) {
        int i = i0 + k * 256;
        float v = W[i];
        if (sel == 2) {
            Wv16[i] = __float2half(v);
        } else if (sel == 3) {
            Wo16[i] = __float2half(v);
        } else {
            bf16 h = __float2bfloat16(v);
            H[base + i] = h;
            L[base + i] = __float2bfloat16(v - __bfloat162float(h));
        }
    }
}

// ---------------- 3-stage pipelined 128x128 GEMM mainloop (16 slabs) -------
#define PG_A   0
#define PG_AL  16384
#define PG_B   32768
#define PG_BL  49152
#define PG_STAGE 65536
#define PG_SMEM  (3 * PG_STAGE)

__device__ __forceinline__ void proj_issue(u32 st,
    const bf16* __restrict__ Ah, const bf16* __restrict__ Al,
    const bf16* __restrict__ Bh, const bf16* __restrict__ Bl, int s)
{
    issue_A128(st + PG_A,  Ah + s * 64, DD);
    issue_A128(st + PG_AL, Al + s * 64, DD);
    issue_B256(st + PG_B,  Bh + (size_t)s * 64 * DD, DD);
    issue_B256(st + PG_BL, Bl + (size_t)s * 64 * DD, DD);
    CPCOMMIT();
}

__device__ __forceinline__ void proj_mainloop(u32 sb,
    const bf16* __restrict__ Ah, const bf16* __restrict__ Al,
    const bf16* __restrict__ Bh, const bf16* __restrict__ Bl,
    int lane, int mwarp, int nwarp, float acc[4][4][4])
{
    proj_issue(sb + 0 * PG_STAGE, Ah, Al, Bh, Bl, 0);
    proj_issue(sb + 1 * PG_STAGE, Ah, Al, Bh, Bl, 1);
    for (int s = 0; s < 16; s++) {
        if (s < 15) { CPWAIT(1); } else { CPWAIT(0); }
        __syncthreads();
        if (s + 2 < 16)
            proj_issue(sb + ((s + 2) % 3) * PG_STAGE, Ah, Al, Bh, Bl, s + 2);
        u32 cur = sb + (s % 3) * PG_STAGE;
        warp_slab<4, 0, 256>(cur + PG_A, cur + PG_AL, cur + PG_B, cur + PG_BL,
                             mwarp, nwarp, lane, acc);
    }
}

// fused QK projection (3-pass bf16): n-dim spans 2*1024
__global__ void __launch_bounds__(256) k_proj_qk(
    const bf16* __restrict__ xh, const bf16* __restrict__ xl,
    const bf16* __restrict__ Whi, const bf16* __restrict__ Wlo,
    const float* __restrict__ bq, const float* __restrict__ bk,
    bf16* __restrict__ Qh, bf16* __restrict__ Ql,
    bf16* __restrict__ Kh, bf16* __restrict__ Kl)
{
    extern __shared__ char sm[];
    u32 sb = smem_u32(sm);
    int ng = blockIdx.x << 7;
    int sel = ng >> 10, ncol = ng & 1023;
    int m0 = blockIdx.y << 7;
    int lane = threadIdx.x & 31, wid = threadIdx.x >> 5;
    int mwarp = (wid >> 2) << 6, nwarp = (wid & 3) << 5;

    const bf16* Ah = xh + (size_t)m0 * DD;
    const bf16* Al = xl + (size_t)m0 * DD;
    const bf16* Bh = Whi + (size_t)sel * DD * DD + ncol;
    const bf16* Bl = Wlo + (size_t)sel * DD * DD + ncol;
    const float* bias = sel == 0 ? bq : bk;
    bf16* Ohi = sel == 0 ? Qh : Kh;
    bf16* Olo = sel == 0 ? Ql : Kl;

    float acc[4][4][4];
#pragma unroll
    for (int i = 0; i < 4; i++)
#pragma unroll
        for (int j = 0; j < 4; j++)
#pragma unroll
            for (int k = 0; k < 4; k++) acc[i][j][k] = 0.0f;

    proj_mainloop(sb, Ah, Al, Bh, Bl, lane, mwarp, nwarp, acc);

    int g = lane >> 2, t = (lane & 3) << 1;
#pragma unroll
    for (int mf = 0; mf < 4; mf++)
#pragma unroll
        for (int half = 0; half < 2; half++) {
            int r = m0 + mwarp + (mf << 4) + g + (half << 3);
#pragma unroll
            for (int nf = 0; nf < 4; nf++) {
                int n = ncol + nwarp + (nf << 3) + t;
                float v0 = acc[mf][nf][half * 2 + 0] + bias[n];
                float v1 = acc[mf][nf][half * 2 + 1] + bias[n + 1];
                split_store2(Ohi + (size_t)r * DD + n, Olo + (size_t)r * DD + n, v0, v1);
            }
        }
}

// ---------------- fp16 1-pass projection machinery --------------------------
#define PO_A 0
#define PO_B 16384
#define PO_STAGE 32768
#define PO_SMEM  98304

__device__ __forceinline__ void po_issue(u32 st, const __half* A,
                                         const __half* W, int s)
{
    issue_A128(st + PO_A, (const bf16*)(A + s * 64), DD);
    issue_B256(st + PO_B, (const bf16*)(W + (size_t)s * 64 * DD), DD);
    CPCOMMIT();
}

__device__ __forceinline__ void po_mainloop(u32 sb, const __half* A,
    const __half* W, int lane, int mwarp, int nwarp, float acc[4][4][4])
{
    po_issue(sb + 0 * PO_STAGE, A, W, 0);
    po_issue(sb + 1 * PO_STAGE, A, W, 1);
    for (int s = 0; s < 16; s++) {
        if (s < 15) { CPWAIT(1); } else { CPWAIT(0); }
        __syncthreads();
        if (s + 2 < 16)
            po_issue(sb + ((s + 2) % 3) * PO_STAGE, A, W, s + 2);
        u32 cur = sb + (s % 3) * PO_STAGE;
        warp_slab_o(cur + PO_A, cur + PO_B, mwarp, nwarp, lane, acc);
    }
}

// V projection: V = (x*delta)@Wv + bv, fp16 in/out, 1-pass
__global__ void __launch_bounds__(256) k_proj_v(
    const __half* __restrict__ xs16, const __half* __restrict__ Wv16,
    const float* __restrict__ bias, __half* __restrict__ Vp)
{
    extern __shared__ char sm[];
    u32 sb = smem_u32(sm);
    int n0 = blockIdx.x << 7, m0 = blockIdx.y << 7;
    int lane = threadIdx.x & 31, wid = threadIdx.x >> 5;
    int mwarp = (wid >> 2) << 6, nwarp = (wid & 3) << 5;

    float acc[4][4][4];
#pragma unroll
    for (int i = 0; i < 4; i++)
#pragma unroll
        for (int j = 0; j < 4; j++)
#pragma unroll
            for (int k = 0; k < 4; k++) acc[i][j][k] = 0.0f;

    po_mainloop(sb, xs16 + (size_t)m0 * DD, Wv16 + n0, lane, mwarp, nwarp, acc);

    int g = lane >> 2, t = (lane & 3) << 1;
#pragma unroll
    for (int mf = 0; mf < 4; mf++)
#pragma unroll
        for (int half = 0; half < 2; half++) {
            int r = m0 + mwarp + (mf << 4) + g + (half << 3);
#pragma unroll
            for (int nf = 0; nf < 4; nf++) {
                int n = n0 + nwarp + (nf << 3) + t;
                *(__half2*)(Vp + (size_t)r * DD + n) =
                    __floats2half2_rn(acc[mf][nf][half*2] + bias[n],
                                      acc[mf][nf][half*2+1] + bias[n + 1]);
            }
        }
}

// out projection: out = C@Wo + bo, fp16 1-pass, fp32 out
__global__ void __launch_bounds__(256) k_proj_o(
    const __half* __restrict__ C16, const __half* __restrict__ W16,
    const float* __restrict__ bias, float* __restrict__ Of)
{
    extern __shared__ char sm[];
    u32 sb = smem_u32(sm);
    int n0 = blockIdx.x << 7, m0 = blockIdx.y << 7;
    int lane = threadIdx.x & 31, wid = threadIdx.x >> 5;
    int mwarp = (wid >> 2) << 6, nwarp = (wid & 3) << 5;

    float acc[4][4][4];
#pragma unroll
    for (int i = 0; i < 4; i++)
#pragma unroll
        for (int j = 0; j < 4; j++)
#pragma unroll
            for (int k = 0; k < 4; k++) acc[i][j][k] = 0.0f;

    po_mainloop(sb, C16 + (size_t)m0 * DD, W16 + n0, lane, mwarp, nwarp, acc);

    int g = lane >> 2, t = (lane & 3) << 1;
#pragma unroll
    for (int mf = 0; mf < 4; mf++)
#pragma unroll
        for (int half = 0; half < 2; half++) {
            int r = m0 + mwarp + (mf << 4) + g + (half << 3);
#pragma unroll
            for (int nf = 0; nf < 4; nf++) {
                int n = n0 + nwarp + (nf << 3) + t;
                float2 o;
                o.x = acc[mf][nf][half * 2 + 0] + bias[n];
                o.y = acc[mf][nf][half * 2 + 1] + bias[n + 1];
                *(float2*)(Of + (size_t)r * DD + n) = o;
            }
        }
}

// ---------------- scores: S = QK^T/8 - 0.1*|m-n| + log(delta_n+1e-6) -------
#define S_AHI 0
#define S_ALO 16384
#define S_BHI 32768
#define S_BLO 49152
#define S_RELB 65536
#define S_SMEM 66560

__global__ void __launch_bounds__(256) k_scores(
    const bf16* __restrict__ Qh, const bf16* __restrict__ Ql,
    const bf16* __restrict__ Kh, const bf16* __restrict__ Kl,
    const float* __restrict__ delta, float* __restrict__ S)
{
    extern __shared__ char sm[];
    u32 sb = smem_u32(sm);
    int z = blockIdx.z, b = z >> 4, h = z & 15;
    int m0 = blockIdx.y << 7, n0 = blockIdx.x << 7;
    int lane = threadIdx.x & 31, wid = threadIdx.x >> 5;
    int mwarp = (wid >> 2) << 6, nwarp = (wid & 3) << 5;

    size_t qoff = (size_t)(b * LL + m0) * DD + h * DK;
    size_t koff = (size_t)(b * LL + n0) * DD + h * DK;
    issue_A128(sb + S_AHI, Qh + qoff, DD);
    issue_A128(sb + S_ALO, Ql + qoff, DD);
    issue_A128(sb + S_BHI, Kh + koff, DD);
    issue_A128(sb + S_BLO, Kl + koff, DD);
    CPCOMMIT();

    float* relb = (float*)(sm + S_RELB);
    if (threadIdx.x < 128)
        relb[threadIdx.x] = logf(delta[b * LL + n0 + threadIdx.x] + 1e-6f);

    float acc[4][4][4];
#pragma unroll
    for (int i = 0; i < 4; i++)
#pragma unroll
        for (int j = 0; j < 4; j++)
#pragma unroll
            for (int k = 0; k < 4; k++) acc[i][j][k] = 0.0f;

    CPWAIT(0);
    __syncthreads();
    warp_slab<3, 1, 128>(sb + S_AHI, sb + S_ALO, sb + S_BHI, sb + S_BLO,
                         mwarp, nwarp, lane, acc);

    int g = lane >> 2, t = (lane & 3) << 1;
#pragma unroll
    for (int mf = 0; mf < 4; mf++)
#pragma unroll
        for (int half = 0; half < 2; half++) {
            int m = m0 + mwarp + (mf << 4) + g + (half << 3);
            float* srow = S + ((size_t)z * LL + m) * LL + n0;
#pragma unroll
            for (int nf = 0; nf < 4; nf++) {
                int nl = nwarp + (nf << 3) + t;
                int n = n0 + nl;
                float2 o;
                o.x = acc[mf][nf][half * 2 + 0] * 0.125f
                    - 0.1f * fabsf((float)(m - n)) + relb[nl];
                o.y = acc[mf][nf][half * 2 + 1] * 0.125f
                    - 0.1f * fabsf((float)(m - n - 1)) + relb[nl + 1];
                *(float2*)(srow + nl) = o;
            }
        }
}

// ---------------- softmax + fp16 probs + mean over heads -------------------
__global__ void __launch_bounds__(256) softmax_mean_kernel(
    const float* __restrict__ S, __half* __restrict__ P,
    float* __restrict__ outm)
{
    int bq = blockIdx.x;
    int b = bq >> 11, q = bq & 2047;
    int tid = threadIdx.x;
    int wid = tid >> 5, lid = tid & 31;
    __shared__ float redm[8], reds[8];
    float macc[8];
#pragma unroll
    for (int j = 0; j < 8; j++) macc[j] = 0.0f;

    for (int h = 0; h < HH; h++) {
        size_t roff = ((size_t)(b * HH + h) * LL + q) * LL;
        const float* row = S + roff;
        float4 v0 = *(const float4*)(row + (tid << 2));
        float4 v1 = *(const float4*)(row + (tid << 2) + 1024);
        float p[8] = {v0.x, v0.y, v0.z, v0.w, v1.x, v1.y, v1.z, v1.w};

        float m = p[0];
#pragma unroll
        for (int j = 1; j < 8; j++) m = fmaxf(m, p[j]);
#pragma unroll
        for (int off = 16; off; off >>= 1) m = fmaxf(m, __shfl_xor_sync(0xffffffffu, m, off));
        if (lid == 0) redm[wid] = m;
        __syncthreads();
        m = redm[0];
#pragma unroll
        for (int w = 1; w < 8; w++) m = fmaxf(m, redm[w]);

        float s = 0.0f;
#pragma unroll
        for (int j = 0; j < 8; j++) { p[j] = fexp(p[j] - m); s += p[j]; }
#pragma unroll
        for (int off = 16; off; off >>= 1) s += __shfl_xor_sync(0xffffffffu, s, off);
        if (lid == 0) reds[wid] = s;
        __syncthreads();
        s = 0.0f;
#pragma unroll
        for (int w = 0; w < 8; w++) s += reds[w];

        float inv = 1.0f / s;
#pragma unroll
        for (int j = 0; j < 8; j++) { p[j] *= inv; macc[j] += p[j]; }

        union { __half2 h[2]; uint2 u; } q0, q1;
        q0.h[0] = __floats2half2_rn(p[0], p[1]);
        q0.h[1] = __floats2half2_rn(p[2], p[3]);
        q1.h[0] = __floats2half2_rn(p[4], p[5]);
        q1.h[1] = __floats2half2_rn(p[6], p[7]);
        *(uint2*)(P + roff + (tid << 2))        = q0.u;
        *(uint2*)(P + roff + (tid << 2) + 1024) = q1.u;
    }

    if (outm) {
        float* o = outm + ((size_t)bq * LL);
        float4 o0, o1;
        o0.x = macc[0] * 0.0625f; o0.y = macc[1] * 0.0625f;
        o0.z = macc[2] * 0.0625f; o0.w = macc[3] * 0.0625f;
        o1.x = macc[4] * 0.0625f; o1.y = macc[5] * 0.0625f;
        o1.z = macc[6] * 0.0625f; o1.w = macc[7] * 0.0625f;
        *(float4*)(o + (tid << 2))        = o0;
        *(float4*)(o + (tid << 2) + 1024) = o1;
    }
}

// ---------------- context: ctx = P @ V (fp16 1-pass) -> C fp16 --------------
#define C_A   0
#define C_B   32768
#define C_STAGE 40960
#define C_SMEM  81920

__device__ __forceinline__ void ctx_issue(u32 st, const __half* Pb,
                                          const __half* Vb, int s)
{
    issue_A256(st + C_A, (const bf16*)(Pb + s * 64), LL);
    issue_B64 (st + C_B, (const bf16*)(Vb + (size_t)s * 64 * DD), DD);
    CPCOMMIT();
}

__global__ void __launch_bounds__(256) k_context(
    const __half* __restrict__ P, const __half* __restrict__ V,
    __half* __restrict__ C16)
{
    extern __shared__ char sm[];
    u32 sb = smem_u32(sm);
    int z = blockIdx.y, b = z >> 4, h = z & 15;
    int m0 = blockIdx.x << 8;
    int lane = threadIdx.x & 31, wid = threadIdx.x >> 5;
    int mwarp = (wid >> 1) << 6, nwarp = (wid & 1) << 5;

    float acc[4][4][4];
#pragma unroll
    for (int i = 0; i < 4; i++)
#pragma unroll
        for (int j = 0; j < 4; j++)
#pragma unroll
            for (int k = 0; k < 4; k++) acc[i][j][k] = 0.0f;

    const __half* Pb = P + (size_t)z * LL * LL + (size_t)m0 * LL;
    const __half* Vb = V + (size_t)b * LL * DD + h * DK;

    ctx_issue(sb, Pb, Vb, 0);
    for (int s = 0; s < LL / 64; s++) {
        CPWAIT(0);
        __syncthreads();
        if (s + 1 < LL / 64)
            ctx_issue(sb + ((s + 1) & 1) * C_STAGE, Pb, Vb, s + 1);
        u32 cur = sb + (s & 1) * C_STAGE;
        warp_slab_h(cur + C_A, cur + C_B, mwarp, nwarp, lane, acc);
    }

    int g = lane >> 2, t = (lane & 3) << 1;
#pragma unroll
    for (int mf = 0; mf < 4; mf++)
#pragma unroll
        for (int half = 0; half < 2; half++) {
            int r = m0 + mwarp + (mf << 4) + g + (half << 3);
            size_t rb = (size_t)(b * LL + r) * DD + h * DK;
#pragma unroll
            for (int nf = 0; nf < 4; nf++) {
                int n = nwarp + (nf << 3) + t;
                *(__half2*)(C16 + rb + n) =
                    __floats2half2_rn(acc[mf][nf][half*2], acc[mf][nf][half*2+1]);
            }
        }
}

// ---------------- launch ----------------------------------------------------
extern "C" void kernel_launch(void* const* d_in, const int* in_sizes, int n_in,
                              void* d_out, int out_size)
{
    const float* x   = (const float*)d_in[0];
    const float* dr  = (const float*)d_in[1];
    const float* Wq  = (const float*)d_in[2];
    const float* bq  = (const float*)d_in[3];
    const float* Wk  = (const float*)d_in[4];
    const float* bk  = (const float*)d_in[5];
    const float* Wv  = (const float*)d_in[6];
    const float* bv  = (const float*)d_in[7];
    const float* Wo  = (const float*)d_in[8];
    const float* bo  = (const float*)d_in[9];
    float* out = (float*)d_out;

    float* pS;
    __half *pP, *pV, *pC16, *pWv16, *pWo16, *pxs16;
    bf16 *pxhi, *pxlo, *pWhi, *pWlo;
    bf16 *pQhi, *pQlo, *pKhi, *pKlo;
    cudaGetSymbolAddress((void**)&pS,    g_S);
    cudaGetSymbolAddress((void**)&pP,    g_P);
    cudaGetSymbolAddress((void**)&pV,    g_V);
    cudaGetSymbolAddress((void**)&pC16,  g_C16);
    cudaGetSymbolAddress((void**)&pWv16, g_Wv16);
    cudaGetSymbolAddress((void**)&pWo16, g_Wo16);
    cudaGetSymbolAddress((void**)&pxs16, g_xs16);
    cudaGetSymbolAddress((void**)&pxhi,  g_xhi);
    cudaGetSymbolAddress((void**)&pxlo,  g_xlo);
    cudaGetSymbolAddress((void**)&pWhi,  g_Whi);
    cudaGetSymbolAddress((void**)&pWlo,  g_Wlo);
    cudaGetSymbolAddress((void**)&pQhi,  g_Qhi);
    cudaGetSymbolAddress((void**)&pQlo,  g_Qlo);
    cudaGetSymbolAddress((void**)&pKhi,  g_Khi);
    cudaGetSymbolAddress((void**)&pKlo,  g_Klo);

    cudaFuncSetAttribute(k_proj_qk, cudaFuncAttributeMaxDynamicSharedMemorySize, PG_SMEM);
    cudaFuncSetAttribute(k_proj_v,  cudaFuncAttributeMaxDynamicSharedMemorySize, PO_SMEM);
    cudaFuncSetAttribute(k_proj_o,  cudaFuncAttributeMaxDynamicSharedMemorySize, PO_SMEM);
    cudaFuncSetAttribute(k_scores,  cudaFuncAttributeMaxDynamicSharedMemorySize, S_SMEM);
    cudaFuncSetAttribute(k_context, cudaFuncAttributeMaxDynamicSharedMemorySize, C_SMEM);

    // converters
    conv_x<<<BL, 256>>>(x, dr, pxhi, pxlo, pxs16);
    dim3 gw(1024, 4);
    conv_w4<<<gw, 256>>>(Wq, Wk, Wv, Wo, pWhi, pWlo, pWv16, pWo16);

    // Q,K projection (3-pass bf16, 3-stage pipeline)
    dim3 gqk(2 * DD / 128, BL / 128);    // (16, 32)
    k_proj_qk<<<gqk, 256, PG_SMEM>>>(pxhi, pxlo, pWhi, pWlo, bq, bk,
                                     pQhi, pQlo, pKhi, pKlo);

    // V projection (fp16 1-pass)
    dim3 gv(DD / 128, BL / 128);         // (8, 32)
    k_proj_v<<<gv, 256, PO_SMEM>>>(pxs16, pWv16, bv, pV);

    // scores -> fp32 S
    dim3 gsc(LL / 128, LL / 128, BB * HH);   // (16, 16, 32)
    k_scores<<<gsc, 256, S_SMEM>>>(pQhi, pQlo, pKhi, pKlo, dr, pS);

    // softmax + fp16 probs + mean
    bool write_mean = (out_size >= (BL * DD + BB * LL * LL));
    softmax_mean_kernel<<<BL, 256>>>(pS, pP,
                                     write_mean ? out + (size_t)BL * DD : nullptr);

    // context (fp16 single-pass) -> C fp16
    dim3 gctx(LL / 256, BB * HH);        // (8, 32)
    k_context<<<gctx, 256, C_SMEM>>>(pP, pV, pC16);

    // output projection (fp16 1-pass, fp32 out + bias)
    k_proj_o<<<gv, 256, PO_SMEM>>>(pC16, pWo16, bo, out);
}

// round 17
// speedup vs baseline: 1.4521x; 1.3001x over previous
#include <cuda_runtime.h>
#include <cuda_bf16.h>
#include <cuda_fp16.h>
#include <math.h>
#include <stdint.h>

#define BB 2
#define LL 2048
#define DD 1024
#define HH 16
#define DK 64
#define BL (BB*LL)              // 4096

typedef unsigned int u32;
typedef __nv_bfloat16 bf16;

// ---------------- scratch (device globals; no allocation allowed) ----------
__device__ float  g_S[(size_t)BB*HH*LL*LL];      // 512 MB raw scores
__device__ __half g_P[(size_t)BB*HH*LL*LL];      // 256 MB probs (fp16)
__device__ bf16   g_xhi [BL*DD], g_xlo [BL*DD];
__device__ bf16   g_xshi[BL*DD], g_xslo[BL*DD];  // x * delta
__device__ bf16   g_Whi[4*DD*DD], g_Wlo[4*DD*DD]; // W hi/lo (q,k,v,o) [k][n]
__device__ bf16   g_Qhi[BL*DD], g_Qlo[BL*DD];
__device__ bf16   g_Khi[BL*DD], g_Klo[BL*DD];
__device__ __half g_V[BL*DD];                    // V (fp16 single)
__device__ bf16   g_Chi[BL*DD], g_Clo[BL*DD];    // context hi/lo

// ---------------- ptx helpers ----------------------------------------------
__device__ __forceinline__ u32 smem_u32(const void* p) {
    u32 a;
    asm("{ .reg .u64 t; cvta.to.shared.u64 t, %1; cvt.u32.u64 %0, t; }"
        : "=r"(a) : "l"(p));
    return a;
}

#define LDSM4(R0,R1,R2,R3,ADDR) \
    asm volatile("ldmatrix.sync.aligned.m8n8.x4.shared.b16 {%0,%1,%2,%3}, [%4];" \
        : "=r"(R0),"=r"(R1),"=r"(R2),"=r"(R3) : "r"(ADDR))
#define LDSM4T(R0,R1,R2,R3,ADDR) \
    asm volatile("ldmatrix.sync.aligned.m8n8.x4.trans.shared.b16 {%0,%1,%2,%3}, [%4];" \
        : "=r"(R0),"=r"(R1),"=r"(R2),"=r"(R3) : "r"(ADDR))

__device__ __forceinline__ void mma16816(float* c, const u32* a, const u32* b) {
    asm volatile(
        "mma.sync.aligned.m16n8k16.row.col.f32.bf16.bf16.f32 "
        "{%0,%1,%2,%3}, {%4,%5,%6,%7}, {%8,%9}, {%0,%1,%2,%3};"
        : "+f"(c[0]), "+f"(c[1]), "+f"(c[2]), "+f"(c[3])
        : "r"(a[0]), "r"(a[1]), "r"(a[2]), "r"(a[3]), "r"(b[0]), "r"(b[1]));
}

__device__ __forceinline__ void mma16816h(float* c, const u32* a, const u32* b) {
    asm volatile(
        "mma.sync.aligned.m16n8k16.row.col.f32.f16.f16.f32 "
        "{%0,%1,%2,%3}, {%4,%5,%6,%7}, {%8,%9}, {%0,%1,%2,%3};"
        : "+f"(c[0]), "+f"(c[1]), "+f"(c[2]), "+f"(c[3])
        : "r"(a[0]), "r"(a[1]), "r"(a[2]), "r"(a[3]), "r"(b[0]), "r"(b[1]));
}

#define CPA16(dst, src) \
    asm volatile("cp.async.cg.shared.global [%0], [%1], 16;" :: "r"(dst), "l"(src))
#define CPCOMMIT() asm volatile("cp.async.commit_group;" ::: "memory")
#define CPWAIT(n)  asm volatile("cp.async.wait_group %0;" :: "n"(n) : "memory")

// ---------------- async staging (swizzled) ----------------------------------
__device__ __forceinline__ void issue_A128(u32 dst, const bf16* A, size_t lda) {
#pragma unroll
    for (int i = 0; i < 4; i++) {
        int idx = threadIdx.x + (i << 8);
        int r = idx >> 3, c = idx & 7;
        int off = (r << 7) | (c << 4);
        CPA16(dst + (off ^ ((off >> 3) & 0x70)), A + (size_t)r * lda + (c << 3));
    }
}
__device__ __forceinline__ void issue_A256(u32 dst, const bf16* A, size_t lda) {
#pragma unroll
    for (int i = 0; i < 8; i++) {
        int idx = threadIdx.x + (i << 8);
        int r = idx >> 3, c = idx & 7;
        int off = (r << 7) | (c << 4);
        CPA16(dst + (off ^ ((off >> 3) & 0x70)), A + (size_t)r * lda + (c << 3));
    }
}
__device__ __forceinline__ void issue_B256(u32 dst, const bf16* B, size_t ldb) {
#pragma unroll
    for (int i = 0; i < 4; i++) {
        int idx = threadIdx.x + (i << 8);
        int r = idx >> 4, c = idx & 15;
        int off = (r << 8) | (c << 4);
        CPA16(dst + (off ^ ((off >> 4) & 0x70)), B + (size_t)r * ldb + (c << 3));
    }
}
__device__ __forceinline__ void issue_B64(u32 dst, const bf16* B, size_t ldb) {
#pragma unroll
    for (int i = 0; i < 2; i++) {
        int idx = threadIdx.x + (i << 8);
        int r = idx >> 3, c = idx & 7;
        int off = (r << 7) | (c << 4);
        CPA16(dst + (off ^ ((off >> 3) & 0x70)), B + (size_t)r * ldb + (c << 3));
    }
}

// ---------------- warp slab: 64x32 warp tile over one 64-deep k-slab -------
// BMODE 0: B staged [k][n] row-major, trans ldmatrix (pitch BPITCH)
// BMODE 1: B staged [n][k] row-major (128B pitch), plain ldmatrix
// 3-pass hi/lo: Ah*Bh + Ah*Bl + Al*Bh
template<int SW, int BMODE, int BPITCH>
__device__ __forceinline__ void warp_slab(
    u32 sAh, u32 sAl, u32 sBh, u32 sBl,
    int mwarp, int nwarp, int lane, float acc[4][4][4])
{
#pragma unroll
    for (int ks = 0; ks < 4; ks++) {
        const int k0 = ks << 4;
        u32 bh[4][2], bl[4][2], a[4][4];
#pragma unroll
        for (int nf = 0; nf < 2; nf++) {
            int off;
            if (BMODE == 0) {
                int kr = k0 + (lane & 15);
                int nc = nwarp + (nf << 4) + ((lane >> 4) << 3);
                off = kr * BPITCH + (nc << 1);
            } else {
                int nr = nwarp + (nf << 4) + (lane & 7) + ((lane >> 4) << 3);
                int kc = k0 + (((lane >> 3) & 1) << 3);
                off = (nr << 7) + (kc << 1);
            }
            int so = off ^ ((off >> SW) & 0x70);
            if (BMODE == 0) {
                LDSM4T(bh[nf*2][0], bh[nf*2][1], bh[nf*2+1][0], bh[nf*2+1][1], sBh + so);
                LDSM4T(bl[nf*2][0], bl[nf*2][1], bl[nf*2+1][0], bl[nf*2+1][1], sBl + so);
            } else {
                LDSM4(bh[nf*2][0], bh[nf*2][1], bh[nf*2+1][0], bh[nf*2+1][1], sBh + so);
                LDSM4(bl[nf*2][0], bl[nf*2][1], bl[nf*2+1][0], bl[nf*2+1][1], sBl + so);
            }
        }
        int arow = mwarp + (lane & 15);
        int acol = (k0 + ((lane >> 4) << 3)) << 1;
#pragma unroll
        for (int mf = 0; mf < 4; mf++) {
            int off = ((arow + (mf << 4)) << 7) + acol;
            int so = off ^ ((off >> 3) & 0x70);
            LDSM4(a[mf][0], a[mf][1], a[mf][2], a[mf][3], sAh + so);
        }
#pragma unroll
        for (int mf = 0; mf < 4; mf++)
#pragma unroll
            for (int nf = 0; nf < 4; nf++) {
                mma16816(acc[mf][nf], a[mf], bh[nf]);
                mma16816(acc[mf][nf], a[mf], bl[nf]);
            }
#pragma unroll
        for (int mf = 0; mf < 4; mf++) {
            int off = ((arow + (mf << 4)) << 7) + acol;
            int so = off ^ ((off >> 3) & 0x70);
            LDSM4(a[mf][0], a[mf][1], a[mf][2], a[mf][3], sAl + so);
        }
#pragma unroll
        for (int mf = 0; mf < 4; mf++)
#pragma unroll
            for (int nf = 0; nf < 4; nf++)
                mma16816(acc[mf][nf], a[mf], bh[nf]);
    }
}

// single-pass fp16 warp slab (context): A [m][k] plain, B [k][n] trans, 128B pitch
__device__ __forceinline__ void warp_slab_h(
    u32 sA, u32 sB, int mwarp, int nwarp, int lane, float acc[4][4][4])
{
#pragma unroll
    for (int ks = 0; ks < 4; ks++) {
        const int k0 = ks << 4;
        u32 b[4][2], a[4][4];
#pragma unroll
        for (int nf = 0; nf < 2; nf++) {
            int kr = k0 + (lane & 15);
            int nc = nwarp + (nf << 4) + ((lane >> 4) << 3);
            int off = (kr << 7) + (nc << 1);
            int so = off ^ ((off >> 3) & 0x70);
            LDSM4T(b[nf*2][0], b[nf*2][1], b[nf*2+1][0], b[nf*2+1][1], sB + so);
        }
        int arow = mwarp + (lane & 15);
        int acol = (k0 + ((lane >> 4) << 3)) << 1;
#pragma unroll
        for (int mf = 0; mf < 4; mf++) {
            int off = ((arow + (mf << 4)) << 7) + acol;
            int so = off ^ ((off >> 3) & 0x70);
            LDSM4(a[mf][0], a[mf][1], a[mf][2], a[mf][3], sA + so);
        }
#pragma unroll
        for (int mf = 0; mf < 4; mf++)
#pragma unroll
            for (int nf = 0; nf < 4; nf++)
                mma16816h(acc[mf][nf], a[mf], b[nf]);
    }
}

__device__ __forceinline__ void split_store2(bf16* H, bf16* L, float v0, float v1) {
    bf16 h0 = __float2bfloat16(v0), h1 = __float2bfloat16(v1);
    bf16 l0 = __float2bfloat16(v0 - __bfloat162float(h0));
    bf16 l1 = __float2bfloat16(v1 - __bfloat162float(h1));
    __nv_bfloat162 hp; hp.x = h0; hp.y = h1;
    __nv_bfloat162 lp; lp.x = l0; lp.y = l1;
    *(__nv_bfloat162*)H = hp;
    *(__nv_bfloat162*)L = lp;
}

__device__ __forceinline__ float fexp(float x) {
    x = fmaxf(x, -87.0f);
    float t = x * 1.4426950408889634f;
    int ei = __float2int_rn(t);
    float f = t - (float)ei;
    float p = 1.5403530e-4f;
    p = fmaf(p, f, 1.3333558e-3f);
    p = fmaf(p, f, 9.6181291e-3f);
    p = fmaf(p, f, 5.5504109e-2f);
    p = fmaf(p, f, 2.4022651e-1f);
    p = fmaf(p, f, 6.9314718e-1f);
    p = fmaf(p, f, 1.0f);
    return p * __int_as_float((ei + 127) << 23);
}

// ---------------- converters ------------------------------------------------
__global__ void __launch_bounds__(256) conv_x(
    const float* __restrict__ x, const float* __restrict__ dr,
    bf16* xh, bf16* xl, bf16* xsh, bf16* xsl)
{
    int i0 = blockIdx.x * 1024 + threadIdx.x;
#pragma unroll
    for (int k = 0; k < 4; k++) {
        int i = i0 + k * 256;
        float v = x[i];
        float d = dr[i >> 10];
        bf16 h = __float2bfloat16(v);
        xh[i] = h; xl[i] = __float2bfloat16(v - __bfloat162float(h));
        float vs = v * d;
        bf16 hs = __float2bfloat16(vs);
        xsh[i] = hs; xsl[i] = __float2bfloat16(vs - __bfloat162float(hs));
    }
}

__global__ void __launch_bounds__(256) conv_w4(
    const float* __restrict__ Wq, const float* __restrict__ Wk,
    const float* __restrict__ Wv, const float* __restrict__ Wo,
    bf16* __restrict__ H, bf16* __restrict__ L)
{
    int sel = blockIdx.y;
    const float* W = sel == 0 ? Wq : (sel == 1 ? Wk : (sel == 2 ? Wv : Wo));
    size_t base = (size_t)sel * DD * DD;
    int i0 = blockIdx.x * 1024 + threadIdx.x;
#pragma unroll
    for (int k = 0; k < 4; k++) {
        int i = i0 + k * 256;
        float v = W[i];
        bf16 h = __float2bfloat16(v);
        H[base + i] = h;
        L[base + i] = __float2bfloat16(v - __bfloat162float(h));
    }
}

// ---------------- 3-stage pipelined 128x128 GEMM mainloop (16 slabs) -------
#define PG_A   0
#define PG_AL  16384
#define PG_B   32768
#define PG_BL  49152
#define PG_STAGE 65536
#define PG_SMEM  (3 * PG_STAGE)

__device__ __forceinline__ void proj_issue(u32 st,
    const bf16* __restrict__ Ah, const bf16* __restrict__ Al,
    const bf16* __restrict__ Bh, const bf16* __restrict__ Bl, int s)
{
    issue_A128(st + PG_A,  Ah + s * 64, DD);
    issue_A128(st + PG_AL, Al + s * 64, DD);
    issue_B256(st + PG_B,  Bh + (size_t)s * 64 * DD, DD);
    issue_B256(st + PG_BL, Bl + (size_t)s * 64 * DD, DD);
    CPCOMMIT();
}

__device__ __forceinline__ void proj_mainloop(u32 sb,
    const bf16* __restrict__ Ah, const bf16* __restrict__ Al,
    const bf16* __restrict__ Bh, const bf16* __restrict__ Bl,
    int lane, int mwarp, int nwarp, float acc[4][4][4])
{
    proj_issue(sb + 0 * PG_STAGE, Ah, Al, Bh, Bl, 0);
    proj_issue(sb + 1 * PG_STAGE, Ah, Al, Bh, Bl, 1);
    for (int s = 0; s < 16; s++) {
        if (s < 15) { CPWAIT(1); } else { CPWAIT(0); }
        __syncthreads();
        if (s + 2 < 16)
            proj_issue(sb + ((s + 2) % 3) * PG_STAGE, Ah, Al, Bh, Bl, s + 2);
        u32 cur = sb + (s % 3) * PG_STAGE;
        warp_slab<4, 0, 256>(cur + PG_A, cur + PG_AL, cur + PG_B, cur + PG_BL,
                             mwarp, nwarp, lane, acc);
    }
}

// fused QKV projection
__global__ void __launch_bounds__(256) k_proj_qkv(
    const bf16* __restrict__ xh, const bf16* __restrict__ xl,
    const bf16* __restrict__ xsh, const bf16* __restrict__ xsl,
    const bf16* __restrict__ Whi, const bf16* __restrict__ Wlo,
    const float* __restrict__ bq, const float* __restrict__ bk,
    const float* __restrict__ bv,
    bf16* __restrict__ Qh, bf16* __restrict__ Ql,
    bf16* __restrict__ Kh, bf16* __restrict__ Kl,
    __half* __restrict__ Vp)
{
    extern __shared__ char sm[];
    u32 sb = smem_u32(sm);
    int ng = blockIdx.x << 7;
    int sel = ng >> 10, ncol = ng & 1023;
    int m0 = blockIdx.y << 7;
    int lane = threadIdx.x & 31, wid = threadIdx.x >> 5;
    int mwarp = (wid >> 2) << 6, nwarp = (wid & 3) << 5;

    const bf16* Ah = (sel == 2 ? xsh : xh) + (size_t)m0 * DD;
    const bf16* Al = (sel == 2 ? xsl : xl) + (size_t)m0 * DD;
    const bf16* Bh = Whi + (size_t)sel * DD * DD + ncol;
    const bf16* Bl = Wlo + (size_t)sel * DD * DD + ncol;
    const float* bias = sel == 0 ? bq : (sel == 1 ? bk : bv);
    bf16* Ohi = sel == 0 ? Qh : Kh;
    bf16* Olo = sel == 0 ? Ql : Kl;

    float acc[4][4][4];
#pragma unroll
    for (int i = 0; i < 4; i++)
#pragma unroll
        for (int j = 0; j < 4; j++)
#pragma unroll
            for (int k = 0; k < 4; k++) acc[i][j][k] = 0.0f;

    proj_mainloop(sb, Ah, Al, Bh, Bl, lane, mwarp, nwarp, acc);

    int g = lane >> 2, t = (lane & 3) << 1;
#pragma unroll
    for (int mf = 0; mf < 4; mf++)
#pragma unroll
        for (int half = 0; half < 2; half++) {
            int r = m0 + mwarp + (mf << 4) + g + (half << 3);
#pragma unroll
            for (int nf = 0; nf < 4; nf++) {
                int n = ncol + nwarp + (nf << 3) + t;
                float v0 = acc[mf][nf][half * 2 + 0] + bias[n];
                float v1 = acc[mf][nf][half * 2 + 1] + bias[n + 1];
                if (sel == 2) {
                    *(__half2*)(Vp + (size_t)r * DD + n) = __floats2half2_rn(v0, v1);
                } else {
                    split_store2(Ohi + (size_t)r * DD + n, Olo + (size_t)r * DD + n, v0, v1);
                }
            }
        }
}

// output projection: fp32 out + bias (3-pass bf16)
__global__ void __launch_bounds__(256) k_proj_o(
    const bf16* __restrict__ Ch, const bf16* __restrict__ Cl,
    const bf16* __restrict__ Whi, const bf16* __restrict__ Wlo,
    const float* __restrict__ bias, float* __restrict__ Of)
{
    extern __shared__ char sm[];
    u32 sb = smem_u32(sm);
    int n0 = blockIdx.x << 7, m0 = blockIdx.y << 7;
    int lane = threadIdx.x & 31, wid = threadIdx.x >> 5;
    int mwarp = (wid >> 2) << 6, nwarp = (wid & 3) << 5;

    float acc[4][4][4];
#pragma unroll
    for (int i = 0; i < 4; i++)
#pragma unroll
        for (int j = 0; j < 4; j++)
#pragma unroll
            for (int k = 0; k < 4; k++) acc[i][j][k] = 0.0f;

    proj_mainloop(sb, Ch + (size_t)m0 * DD, Cl + (size_t)m0 * DD,
                  Whi + n0, Wlo + n0, lane, mwarp, nwarp, acc);

    int g = lane >> 2, t = (lane & 3) << 1;
#pragma unroll
    for (int mf = 0; mf < 4; mf++)
#pragma unroll
        for (int half = 0; half < 2; half++) {
            int r = m0 + mwarp + (mf << 4) + g + (half << 3);
#pragma unroll
            for (int nf = 0; nf < 4; nf++) {
                int n = n0 + nwarp + (nf << 3) + t;
                float2 o;
                o.x = acc[mf][nf][half * 2 + 0] + bias[n];
                o.y = acc[mf][nf][half * 2 + 1] + bias[n + 1];
                *(float2*)(Of + (size_t)r * DD + n) = o;
            }
        }
}

// ---------------- scores: S = QK^T/8 - 0.1*|m-n| + log(delta_n+1e-6) -------
#define S_AHI 0
#define S_ALO 16384
#define S_BHI 32768
#define S_BLO 49152
#define S_RELB 65536
#define S_SMEM 66560

__global__ void __launch_bounds__(256, 2) k_scores(
    const bf16* __restrict__ Qh, const bf16* __restrict__ Ql,
    const bf16* __restrict__ Kh, const bf16* __restrict__ Kl,
    const float* __restrict__ delta, float* __restrict__ S)
{
    extern __shared__ char sm[];
    u32 sb = smem_u32(sm);
    int z = blockIdx.z, b = z >> 4, h = z & 15;
    int m0 = blockIdx.y << 7, n0 = blockIdx.x << 7;
    int lane = threadIdx.x & 31, wid = threadIdx.x >> 5;
    int mwarp = (wid >> 2) << 6, nwarp = (wid & 3) << 5;

    size_t qoff = (size_t)(b * LL + m0) * DD + h * DK;
    size_t koff = (size_t)(b * LL + n0) * DD + h * DK;
    issue_A128(sb + S_AHI, Qh + qoff, DD);
    issue_A128(sb + S_ALO, Ql + qoff, DD);
    issue_A128(sb + S_BHI, Kh + koff, DD);
    issue_A128(sb + S_BLO, Kl + koff, DD);
    CPCOMMIT();

    float* relb = (float*)(sm + S_RELB);
    if (threadIdx.x < 128)
        relb[threadIdx.x] = logf(delta[b * LL + n0 + threadIdx.x] + 1e-6f);

    float acc[4][4][4];
#pragma unroll
    for (int i = 0; i < 4; i++)
#pragma unroll
        for (int j = 0; j < 4; j++)
#pragma unroll
            for (int k = 0; k < 4; k++) acc[i][j][k] = 0.0f;

    CPWAIT(0);
    __syncthreads();
    warp_slab<3, 1, 128>(sb + S_AHI, sb + S_ALO, sb + S_BHI, sb + S_BLO,
                         mwarp, nwarp, lane, acc);

    int g = lane >> 2, t = (lane & 3) << 1;
#pragma unroll
    for (int mf = 0; mf < 4; mf++)
#pragma unroll
        for (int half = 0; half < 2; half++) {
            int m = m0 + mwarp + (mf << 4) + g + (half << 3);
            float* srow = S + ((size_t)z * LL + m) * LL + n0;
#pragma unroll
            for (int nf = 0; nf < 4; nf++) {
                int nl = nwarp + (nf << 3) + t;
                int n = n0 + nl;
                float2 o;
                o.x = acc[mf][nf][half * 2 + 0] * 0.125f
                    - 0.1f * fabsf((float)(m - n)) + relb[nl];
                o.y = acc[mf][nf][half * 2 + 1] * 0.125f
                    - 0.1f * fabsf((float)(m - n - 1)) + relb[nl + 1];
                *(float2*)(srow + nl) = o;
            }
        }
}

// ---------------- context: ctx = P @ V (fp16 1-pass) ------------------------
#define C_A   0
#define C_B   32768
#define C_STAGE 40960
#define C_SMEM  81920

__device__ __forceinline__ void ctx_issue(u32 st, const __half* Pb,
                                          const __half* Vb, int s)
{
    issue_A256(st + C_A, (const bf16*)(Pb + s * 64), LL);
    issue_B64 (st + C_B, (const bf16*)(Vb + (size_t)s * 64 * DD), DD);
    CPCOMMIT();
}

__global__ void __launch_bounds__(256, 2) k_context(
    const __half* __restrict__ P, const __half* __restrict__ V,
    bf16* __restrict__ Chi, bf16* __restrict__ Clo)
{
    extern __shared__ char sm[];
    u32 sb = smem_u32(sm);
    int z = blockIdx.y, b = z >> 4, h = z & 15;
    int m0 = blockIdx.x << 8;
    int lane = threadIdx.x & 31, wid = threadIdx.x >> 5;
    int mwarp = (wid >> 1) << 6, nwarp = (wid & 1) << 5;

    float acc[4][4][4];
#pragma unroll
    for (int i = 0; i < 4; i++)
#pragma unroll
        for (int j = 0; j < 4; j++)
#pragma unroll
            for (int k = 0; k < 4; k++) acc[i][j][k] = 0.0f;

    const __half* Pb = P + (size_t)z * LL * LL + (size_t)m0 * LL;
    const __half* Vb = V + (size_t)b * LL * DD + h * DK;

    ctx_issue(sb, Pb, Vb, 0);
    for (int s = 0; s < LL / 64; s++) {
        CPWAIT(0);
        __syncthreads();
        if (s + 1 < LL / 64)
            ctx_issue(sb + ((s + 1) & 1) * C_STAGE, Pb, Vb, s + 1);
        u32 cur = sb + (s & 1) * C_STAGE;
        warp_slab_h(cur + C_A, cur + C_B, mwarp, nwarp, lane, acc);
    }

    int g = lane >> 2, t = (lane & 3) << 1;
#pragma unroll
    for (int mf = 0; mf < 4; mf++)
#pragma unroll
        for (int half = 0; half < 2; half++) {
            int r = m0 + mwarp + (mf << 4) + g + (half << 3);
            size_t rb = (size_t)(b * LL + r) * DD + h * DK;
#pragma unroll
            for (int nf = 0; nf < 4; nf++) {
                int n = nwarp + (nf << 3) + t;
                split_store2(Chi + rb + n, Clo + rb + n,
                             acc[mf][nf][half * 2 + 0], acc[mf][nf][half * 2 + 1]);
            }
        }
}

// ---------------- softmax + fp16 probs + mean over heads -------------------
__global__ void __launch_bounds__(256) softmax_mean_kernel(
    const float* __restrict__ S, __half* __restrict__ P,
    float* __restrict__ outm)
{
    int bq = blockIdx.x;
    int b = bq >> 11, q = bq & 2047;
    int tid = threadIdx.x;
    int wid = tid >> 5, lid = tid & 31;
    __shared__ float redm[8], reds[8];
    float macc[8];
#pragma unroll
    for (int j = 0; j < 8; j++) macc[j] = 0.0f;

    for (int h = 0; h < HH; h++) {
        size_t roff = ((size_t)(b * HH + h) * LL + q) * LL;
        const float* row = S + roff;
        float4 v0 = *(const float4*)(row + (tid << 2));
        float4 v1 = *(const float4*)(row + (tid << 2) + 1024);
        float p[8] = {v0.x, v0.y, v0.z, v0.w, v1.x, v1.y, v1.z, v1.w};

        float m = p[0];
#pragma unroll
        for (int j = 1; j < 8; j++) m = fmaxf(m, p[j]);
#pragma unroll
        for (int off = 16; off; off >>= 1) m = fmaxf(m, __shfl_xor_sync(0xffffffffu, m, off));
        if (lid == 0) redm[wid] = m;
        __syncthreads();
        m = redm[0];
#pragma unroll
        for (int w = 1; w < 8; w++) m = fmaxf(m, redm[w]);

        float s = 0.0f;
#pragma unroll
        for (int j = 0; j < 8; j++) { p[j] = fexp(p[j] - m); s += p[j]; }
#pragma unroll
        for (int off = 16; off; off >>= 1) s += __shfl_xor_sync(0xffffffffu, s, off);
        if (lid == 0) reds[wid] = s;
        __syncthreads();
        s = 0.0f;
#pragma unroll
        for (int w = 0; w < 8; w++) s += reds[w];

        float inv = 1.0f / s;
#pragma unroll
        for (int j = 0; j < 8; j++) { p[j] *= inv; macc[j] += p[j]; }

        union { __half2 h[2]; uint2 u; } q0, q1;
        q0.h[0] = __floats2half2_rn(p[0], p[1]);
        q0.h[1] = __floats2half2_rn(p[2], p[3]);
        q1.h[0] = __floats2half2_rn(p[4], p[5]);
        q1.h[1] = __floats2half2_rn(p[6], p[7]);
        *(uint2*)(P + roff + (tid << 2))        = q0.u;
        *(uint2*)(P + roff + (tid << 2) + 1024) = q1.u;
    }

    if (outm) {
        float* o = outm + ((size_t)bq * LL);
        float4 o0, o1;
        o0.x = macc[0] * 0.0625f; o0.y = macc[1] * 0.0625f;
        o0.z = macc[2] * 0.0625f; o0.w = macc[3] * 0.0625f;
        o1.x = macc[4] * 0.0625f; o1.y = macc[5] * 0.0625f;
        o1.z = macc[6] * 0.0625f; o1.w = macc[7] * 0.0625f;
        *(float4*)(o + (tid << 2))        = o0;
        *(float4*)(o + (tid << 2) + 1024) = o1;
    }
}

// ---------------- launch ----------------------------------------------------
extern "C" void kernel_launch(void* const* d_in, const int* in_sizes, int n_in,
                              void* d_out, int out_size)
{
    const float* x   = (const float*)d_in[0];
    const float* dr  = (const float*)d_in[1];
    const float* Wq  = (const float*)d_in[2];
    const float* bq  = (const float*)d_in[3];
    const float* Wk  = (const float*)d_in[4];
    const float* bk  = (const float*)d_in[5];
    const float* Wv  = (const float*)d_in[6];
    const float* bv  = (const float*)d_in[7];
    const float* Wo  = (const float*)d_in[8];
    const float* bo  = (const float*)d_in[9];
    float* out = (float*)d_out;

    float* pS;
    __half *pP, *pV;
    bf16 *pxhi, *pxlo, *pxshi, *pxslo, *pWhi, *pWlo;
    bf16 *pQhi, *pQlo, *pKhi, *pKlo, *pChi, *pClo;
    cudaGetSymbolAddress((void**)&pS,    g_S);
    cudaGetSymbolAddress((void**)&pP,    g_P);
    cudaGetSymbolAddress((void**)&pV,    g_V);
    cudaGetSymbolAddress((void**)&pxhi,  g_xhi);
    cudaGetSymbolAddress((void**)&pxlo,  g_xlo);
    cudaGetSymbolAddress((void**)&pxshi, g_xshi);
    cudaGetSymbolAddress((void**)&pxslo, g_xslo);
    cudaGetSymbolAddress((void**)&pWhi,  g_Whi);
    cudaGetSymbolAddress((void**)&pWlo,  g_Wlo);
    cudaGetSymbolAddress((void**)&pQhi,  g_Qhi);
    cudaGetSymbolAddress((void**)&pQlo,  g_Qlo);
    cudaGetSymbolAddress((void**)&pKhi,  g_Khi);
    cudaGetSymbolAddress((void**)&pKlo,  g_Klo);
    cudaGetSymbolAddress((void**)&pChi,  g_Chi);
    cudaGetSymbolAddress((void**)&pClo,  g_Clo);

    cudaFuncSetAttribute(k_proj_qkv, cudaFuncAttributeMaxDynamicSharedMemorySize, PG_SMEM);
    cudaFuncSetAttribute(k_proj_o,   cudaFuncAttributeMaxDynamicSharedMemorySize, PG_SMEM);
    cudaFuncSetAttribute(k_scores,   cudaFuncAttributeMaxDynamicSharedMemorySize, S_SMEM);
    cudaFuncSetAttribute(k_context,  cudaFuncAttributeMaxDynamicSharedMemorySize, C_SMEM);

    // converters
    conv_x<<<BL, 256>>>(x, dr, pxhi, pxlo, pxshi, pxslo);
    dim3 gw(1024, 4);
    conv_w4<<<gw, 256>>>(Wq, Wk, Wv, Wo, pWhi, pWlo);

    // fused QKV projection (3-stage pipelined HMMA)
    dim3 gqkv(3 * DD / 128, BL / 128);   // (24, 32)
    k_proj_qkv<<<gqkv, 256, PG_SMEM>>>(pxhi, pxlo, pxshi, pxslo, pWhi, pWlo,
                                       bq, bk, bv,
                                       pQhi, pQlo, pKhi, pKlo, pV);

    // scores -> fp32 S
    dim3 gsc(LL / 128, LL / 128, BB * HH);   // (16, 16, 32)
    k_scores<<<gsc, 256, S_SMEM>>>(pQhi, pQlo, pKhi, pKlo, dr, pS);

    // softmax + fp16 probs + mean
    bool write_mean = (out_size >= (BL * DD + BB * LL * LL));
    softmax_mean_kernel<<<BL, 256>>>(pS, pP,
                                     write_mean ? out + (size_t)BL * DD : nullptr);

    // context (fp16 single-pass, 2-stage single-sync pipelined)
    dim3 gctx(LL / 256, BB * HH);        // (8, 32)
    k_context<<<gctx, 256, C_SMEM>>>(pP, pV, pChi, pClo);

    // output projection (3-pass bf16, fp32 out + bias)
    dim3 go(DD / 128, BL / 128);         // (8, 32)
    k_proj_o<<<go, 256, PG_SMEM>>>(pChi, pClo, pWhi + 3 * DD * DD, pWlo + 3 * DD * DD,
                                   bo, out);
}